// round 3
// baseline (speedup 1.0000x reference)
#include <cuda_runtime.h>
#include <cuda_bf16.h>

#define N_NODES 50000
#define DH 256
#define DOUT 64
#define SLOPE 0.01f

// Scratch (allocation-free rule: __device__ globals)
__device__ float g_h[(size_t)N_NODES * DH];      // GEMM output per layer
__device__ int   g_deg[N_NODES];
__device__ float g_dinv[N_NODES];

// ---------------------------------------------------------------------------
// degree / normalization
// ---------------------------------------------------------------------------
__global__ void zero_deg_kernel(int n) {
    int i = blockIdx.x * blockDim.x + threadIdx.x;
    if (i < n) g_deg[i] = 0;
}

__global__ void count_deg_kernel(const int* __restrict__ dst, int E) {
    int i = blockIdx.x * blockDim.x + threadIdx.x;
    if (i < E) atomicAdd(&g_deg[dst[i]], 1);
}

__global__ void dinv_kernel(int n) {
    int i = blockIdx.x * blockDim.x + threadIdx.x;
    if (i < n) g_dinv[i] = rsqrtf((float)(g_deg[i] + 1));  // +1 self loop
}

// ---------------------------------------------------------------------------
// SGEMM: C[M,N] = A[M,K] @ W[N,K]^T   (row-major A, row-major W)
// ---------------------------------------------------------------------------
template <int BM, int BN, int BK, int TM, int TN>
__global__ void __launch_bounds__((BM / TM) * (BN / TN))
sgemm_xwT(const float* __restrict__ A, const float* __restrict__ W,
          float* __restrict__ C, int M, int N, int K) {
    constexpr int THREADS = (BM / TM) * (BN / TN);
    __shared__ float As[BK][BM];
    __shared__ float Ws[BK][BN];

    const int tid = threadIdx.x;
    const int block_m = blockIdx.y * BM;
    const int block_n = blockIdx.x * BN;
    const int tcol = tid % (BN / TN);   // tile col index (N dim)
    const int trow = tid / (BN / TN);   // tile row index (M dim)

    float acc[TM][TN];
#pragma unroll
    for (int i = 0; i < TM; i++)
#pragma unroll
        for (int j = 0; j < TN; j++) acc[i][j] = 0.0f;

    for (int k0 = 0; k0 < K; k0 += BK) {
        // load A tile (BM x BK), transposed into As[k][m]
#pragma unroll
        for (int i = tid; i < BM * BK; i += THREADS) {
            int m = i / BK, k = i % BK;
            int gm = block_m + m;
            As[k][m] = (gm < M) ? A[(size_t)gm * K + k0 + k] : 0.0f;
        }
        // load W tile (BN x BK), transposed into Ws[k][n]
#pragma unroll
        for (int i = tid; i < BN * BK; i += THREADS) {
            int n = i / BK, k = i % BK;
            Ws[k][n] = W[(size_t)(block_n + n) * K + k0 + k];
        }
        __syncthreads();

#pragma unroll
        for (int k = 0; k < BK; k++) {
            float ra[TM], rb[TN];
#pragma unroll
            for (int i = 0; i < TM; i++) ra[i] = As[k][trow * TM + i];
#pragma unroll
            for (int j = 0; j < TN; j++) rb[j] = Ws[k][tcol * TN + j];
#pragma unroll
            for (int i = 0; i < TM; i++)
#pragma unroll
                for (int j = 0; j < TN; j++) acc[i][j] = fmaf(ra[i], rb[j], acc[i][j]);
        }
        __syncthreads();
    }

#pragma unroll
    for (int i = 0; i < TM; i++) {
        int gm = block_m + trow * TM + i;
        if (gm < M) {
#pragma unroll
            for (int j = 0; j < TN; j++) {
                C[(size_t)gm * N + block_n + tcol * TN + j] = acc[i][j];
            }
        }
    }
}

// ---------------------------------------------------------------------------
// self-loop init: out[i] = dinv[i]^2 * h[i]   (vectorized float4)
// ---------------------------------------------------------------------------
template <int D>
__global__ void init_self_kernel(const float* __restrict__ h, float* __restrict__ out, int n) {
    int idx = blockIdx.x * blockDim.x + threadIdx.x;
    int total = n * (D / 4);
    if (idx >= total) return;
    int node = idx / (D / 4);
    float w = g_dinv[node];
    w = w * w;
    float4 v = ((const float4*)h)[idx];
    v.x *= w; v.y *= w; v.z *= w; v.w *= w;
    ((float4*)out)[idx] = v;
}

// ---------------------------------------------------------------------------
// edge scatter: out[dst] += dinv[src]*dinv[dst] * h[src]
// one warp per edge, vectorized red.global.add.v4.f32 (no read-back)
// ---------------------------------------------------------------------------
__device__ __forceinline__ void red_add_v4(float4* addr, float4 v) {
    asm volatile("red.global.add.v4.f32 [%0], {%1, %2, %3, %4};"
                 :: "l"(addr), "f"(v.x), "f"(v.y), "f"(v.z), "f"(v.w)
                 : "memory");
}

template <int D>
__global__ void scatter_edges_kernel(const float* __restrict__ h,
                                     const int* __restrict__ src,
                                     const int* __restrict__ dst,
                                     float* __restrict__ out, int E) {
    int gwarp = (blockIdx.x * blockDim.x + threadIdx.x) >> 5;
    int lane = threadIdx.x & 31;
    int nwarps = (gridDim.x * blockDim.x) >> 5;
    for (int e = gwarp; e < E; e += nwarps) {
        int s = __ldg(&src[e]);
        int d = __ldg(&dst[e]);
        float norm = g_dinv[s] * g_dinv[d];
        const float4* hp = (const float4*)(h + (size_t)s * D);
        float4* op = (float4*)(out + (size_t)d * D);
#pragma unroll
        for (int i = lane; i < D / 4; i += 32) {
            float4 v = hp[i];
            v.x *= norm; v.y *= norm; v.z *= norm; v.w *= norm;
            red_add_v4(&op[i], v);
        }
    }
}

// ---------------------------------------------------------------------------
// finalize: out = (leaky_relu?)(out + b)
// ---------------------------------------------------------------------------
template <int D, bool ACT>
__global__ void finalize_kernel(float* __restrict__ out, const float* __restrict__ b, int n) {
    int idx = blockIdx.x * blockDim.x + threadIdx.x;
    int total = n * (D / 4);
    if (idx >= total) return;
    int c4 = idx % (D / 4);
    float4 bb = ((const float4*)b)[c4];
    float4 v = ((float4*)out)[idx];
    v.x += bb.x; v.y += bb.y; v.z += bb.z; v.w += bb.w;
    if (ACT) {
        v.x = v.x > 0.0f ? v.x : SLOPE * v.x;
        v.y = v.y > 0.0f ? v.y : SLOPE * v.y;
        v.z = v.z > 0.0f ? v.z : SLOPE * v.z;
        v.w = v.w > 0.0f ? v.w : SLOPE * v.w;
    }
    ((float4*)out)[idx] = v;
}

// ---------------------------------------------------------------------------
// launch
// ---------------------------------------------------------------------------
extern "C" void kernel_launch(void* const* d_in, const int* in_sizes, int n_in,
                              void* d_out, int out_size) {
    const float* x  = (const float*)d_in[0];
    const int*   ei = (const int*)d_in[1];
    const float* W1 = (const float*)d_in[2];
    const float* b1 = (const float*)d_in[3];
    const float* W2 = (const float*)d_in[4];
    const float* b2 = (const float*)d_in[5];
    const float* W3 = (const float*)d_in[6];
    const float* b3 = (const float*)d_in[7];
    float* out = (float*)d_out;

    const int N = in_sizes[0] / DH;        // 50000
    const int E = in_sizes[1] / 2;         // 800000
    const int* src = ei;
    const int* dstp = ei + E;

    float* h1 = out;
    float* h2 = out + (size_t)N * DH;
    float* lg = out + 2 * (size_t)N * DH;

    float* hbuf = nullptr;
    cudaGetSymbolAddress((void**)&hbuf, g_h);

    // --- normalization (shared across layers) ---
    zero_deg_kernel<<<(N + 255) / 256, 256>>>(N);
    count_deg_kernel<<<(E + 255) / 256, 256>>>(dstp, E);
    dinv_kernel<<<(N + 255) / 256, 256>>>(N);

    const int scatter_blocks = (E + 7) / 8;  // 8 warps/block, 1 edge/warp

    // --- layer 1: x[N,256] -> h1[N,256] ---
    {
        dim3 grid(DH / 128, (N + 127) / 128);
        sgemm_xwT<128, 128, 8, 8, 8><<<grid, 256>>>(x, W1, hbuf, N, DH, DH);
        int tot4 = N * (DH / 4);
        init_self_kernel<DH><<<(tot4 + 255) / 256, 256>>>(hbuf, h1, N);
        scatter_edges_kernel<DH><<<scatter_blocks, 256>>>(hbuf, src, dstp, h1, E);
        finalize_kernel<DH, true><<<(tot4 + 255) / 256, 256>>>(h1, b1, N);
    }

    // --- layer 2: h1[N,256] -> h2[N,256] ---
    {
        dim3 grid(DH / 128, (N + 127) / 128);
        sgemm_xwT<128, 128, 8, 8, 8><<<grid, 256>>>(h1, W2, hbuf, N, DH, DH);
        int tot4 = N * (DH / 4);
        init_self_kernel<DH><<<(tot4 + 255) / 256, 256>>>(hbuf, h2, N);
        scatter_edges_kernel<DH><<<scatter_blocks, 256>>>(hbuf, src, dstp, h2, E);
        finalize_kernel<DH, true><<<(tot4 + 255) / 256, 256>>>(h2, b2, N);
    }

    // --- layer 3: h2[N,256] -> logits[N,64], no activation ---
    {
        dim3 grid(DOUT / 64, (N + 127) / 128);
        sgemm_xwT<128, 64, 8, 8, 4><<<grid, 256>>>(h2, W3, hbuf, N, DOUT, DH);
        int tot4 = N * (DOUT / 4);
        init_self_kernel<DOUT><<<(tot4 + 255) / 256, 256>>>(hbuf, lg, N);
        scatter_edges_kernel<DOUT><<<scatter_blocks, 256>>>(hbuf, src, dstp, lg, E);
        finalize_kernel<DOUT, false><<<(tot4 + 255) / 256, 256>>>(lg, b3, N);
    }
}

// round 4
// speedup vs baseline: 1.3062x; 1.3062x over previous
#include <cuda_runtime.h>
#include <cuda_bf16.h>

#define N_NODES 50000
#define DH 256
#define DOUT 64
#define SLOPE 0.01f

// Scratch (allocation-free rule: __device__ globals)
__device__ float g_h[(size_t)N_NODES * DH];      // GEMM output per layer
__device__ int   g_deg[N_NODES];
__device__ float g_dinv[N_NODES];

// ---------------------------------------------------------------------------
// degree / normalization
// ---------------------------------------------------------------------------
__global__ void zero_deg_kernel(int n) {
    int i = blockIdx.x * blockDim.x + threadIdx.x;
    if (i < n) g_deg[i] = 0;
}

__global__ void count_deg_kernel(const int* __restrict__ dst, int E) {
    int i = blockIdx.x * blockDim.x + threadIdx.x;
    if (i < E) atomicAdd(&g_deg[dst[i]], 1);
}

__global__ void dinv_kernel(int n) {
    int i = blockIdx.x * blockDim.x + threadIdx.x;
    if (i < n) g_dinv[i] = rsqrtf((float)(g_deg[i] + 1));  // +1 self loop
}

// ---------------------------------------------------------------------------
// SGEMM: C[M,N] = A[M,K] @ W[N,K]^T  (row-major A, row-major W)
// Fused epilogue: Ch = C (for scatter gather), Cout = dinv[m]^2 * C (self loop)
// Register-staged double buffering, BK=16, vectorized LDG/LDS/STG.
// ---------------------------------------------------------------------------
template <int BM, int BN, int BK, int TM, int TN>
__global__ void __launch_bounds__((BM / TM) * (BN / TN), 2)
sgemm_fused(const float* __restrict__ A, const float* __restrict__ W,
            float* __restrict__ Ch, float* __restrict__ Cout,
            int M, int N, int K) {
    constexpr int THREADS = (BM / TM) * (BN / TN);
    constexpr int KV = BK / 4;                       // float4 per row of tile
    constexpr int NA = (BM * BK) / (4 * THREADS);    // float4 loads of A per thread
    constexpr int NW = (BN * BK) / (4 * THREADS);    // float4 loads of W per thread

    __shared__ float As[BK][BM + 4];
    __shared__ float Ws[BK][BN + 4];

    const int tid = threadIdx.x;
    const int block_m = blockIdx.y * BM;
    const int block_n = blockIdx.x * BN;
    const int tcol = tid % (BN / TN);
    const int trow = tid / (BN / TN);

    float acc[TM][TN];
#pragma unroll
    for (int i = 0; i < TM; i++)
#pragma unroll
        for (int j = 0; j < TN; j++) acc[i][j] = 0.0f;

    float4 pa[NA];
    float4 pw[NW];
    const float4 fz = make_float4(0.f, 0.f, 0.f, 0.f);

    // ---- prologue: load tile k0=0 ----
#pragma unroll
    for (int i = 0; i < NA; i++) {
        int idx = tid + i * THREADS;
        int row = idx / KV, c4 = idx % KV;
        int gm = block_m + row;
        pa[i] = (gm < M) ? *(const float4*)&A[(size_t)gm * K + c4 * 4] : fz;
    }
#pragma unroll
    for (int i = 0; i < NW; i++) {
        int idx = tid + i * THREADS;
        int row = idx / KV, c4 = idx % KV;
        pw[i] = *(const float4*)&W[(size_t)(block_n + row) * K + c4 * 4];
    }
#pragma unroll
    for (int i = 0; i < NA; i++) {
        int idx = tid + i * THREADS;
        int row = idx / KV, c4 = idx % KV;
        As[c4 * 4 + 0][row] = pa[i].x;
        As[c4 * 4 + 1][row] = pa[i].y;
        As[c4 * 4 + 2][row] = pa[i].z;
        As[c4 * 4 + 3][row] = pa[i].w;
    }
#pragma unroll
    for (int i = 0; i < NW; i++) {
        int idx = tid + i * THREADS;
        int row = idx / KV, c4 = idx % KV;
        Ws[c4 * 4 + 0][row] = pw[i].x;
        Ws[c4 * 4 + 1][row] = pw[i].y;
        Ws[c4 * 4 + 2][row] = pw[i].z;
        Ws[c4 * 4 + 3][row] = pw[i].w;
    }
    __syncthreads();

    // ---- main loop: prefetch next tile while computing current ----
    for (int k0 = BK; k0 < K; k0 += BK) {
#pragma unroll
        for (int i = 0; i < NA; i++) {
            int idx = tid + i * THREADS;
            int row = idx / KV, c4 = idx % KV;
            int gm = block_m + row;
            pa[i] = (gm < M) ? *(const float4*)&A[(size_t)gm * K + k0 + c4 * 4] : fz;
        }
#pragma unroll
        for (int i = 0; i < NW; i++) {
            int idx = tid + i * THREADS;
            int row = idx / KV, c4 = idx % KV;
            pw[i] = *(const float4*)&W[(size_t)(block_n + row) * K + k0 + c4 * 4];
        }

#pragma unroll
        for (int k = 0; k < BK; k++) {
            float ra[TM], rb[TN];
#pragma unroll
            for (int v = 0; v < TM / 4; v++)
                *(float4*)&ra[v * 4] = *(const float4*)&As[k][trow * TM + v * 4];
#pragma unroll
            for (int v = 0; v < TN / 4; v++)
                *(float4*)&rb[v * 4] = *(const float4*)&Ws[k][tcol * TN + v * 4];
#pragma unroll
            for (int i = 0; i < TM; i++)
#pragma unroll
                for (int j = 0; j < TN; j++) acc[i][j] = fmaf(ra[i], rb[j], acc[i][j]);
        }
        __syncthreads();

#pragma unroll
        for (int i = 0; i < NA; i++) {
            int idx = tid + i * THREADS;
            int row = idx / KV, c4 = idx % KV;
            As[c4 * 4 + 0][row] = pa[i].x;
            As[c4 * 4 + 1][row] = pa[i].y;
            As[c4 * 4 + 2][row] = pa[i].z;
            As[c4 * 4 + 3][row] = pa[i].w;
        }
#pragma unroll
        for (int i = 0; i < NW; i++) {
            int idx = tid + i * THREADS;
            int row = idx / KV, c4 = idx % KV;
            Ws[c4 * 4 + 0][row] = pw[i].x;
            Ws[c4 * 4 + 1][row] = pw[i].y;
            Ws[c4 * 4 + 2][row] = pw[i].z;
            Ws[c4 * 4 + 3][row] = pw[i].w;
        }
        __syncthreads();
    }

    // ---- last tile compute ----
#pragma unroll
    for (int k = 0; k < BK; k++) {
        float ra[TM], rb[TN];
#pragma unroll
        for (int v = 0; v < TM / 4; v++)
            *(float4*)&ra[v * 4] = *(const float4*)&As[k][trow * TM + v * 4];
#pragma unroll
        for (int v = 0; v < TN / 4; v++)
            *(float4*)&rb[v * 4] = *(const float4*)&Ws[k][tcol * TN + v * 4];
#pragma unroll
        for (int i = 0; i < TM; i++)
#pragma unroll
            for (int j = 0; j < TN; j++) acc[i][j] = fmaf(ra[i], rb[j], acc[i][j]);
    }

    // ---- epilogue: Ch = acc ; Cout = dinv^2 * acc ----
#pragma unroll
    for (int i = 0; i < TM; i++) {
        int gm = block_m + trow * TM + i;
        if (gm < M) {
            float w = g_dinv[gm];
            w = w * w;
#pragma unroll
            for (int v = 0; v < TN / 4; v++) {
                size_t off = (size_t)gm * N + block_n + tcol * TN + v * 4;
                float4 hv = make_float4(acc[i][v * 4 + 0], acc[i][v * 4 + 1],
                                        acc[i][v * 4 + 2], acc[i][v * 4 + 3]);
                *(float4*)&Ch[off] = hv;
                float4 ov = make_float4(hv.x * w, hv.y * w, hv.z * w, hv.w * w);
                *(float4*)&Cout[off] = ov;
            }
        }
    }
}

// ---------------------------------------------------------------------------
// edge scatter: out[dst] += dinv[src]*dinv[dst] * h[src]
// one warp per edge, vectorized red.global.add.v4.f32 (no read-back)
// ---------------------------------------------------------------------------
__device__ __forceinline__ void red_add_v4(float4* addr, float4 v) {
    asm volatile("red.global.add.v4.f32 [%0], {%1, %2, %3, %4};"
                 :: "l"(addr), "f"(v.x), "f"(v.y), "f"(v.z), "f"(v.w)
                 : "memory");
}

template <int D>
__global__ void scatter_edges_kernel(const float* __restrict__ h,
                                     const int* __restrict__ src,
                                     const int* __restrict__ dst,
                                     float* __restrict__ out, int E) {
    int gwarp = (blockIdx.x * blockDim.x + threadIdx.x) >> 5;
    int lane = threadIdx.x & 31;
    int nwarps = (gridDim.x * blockDim.x) >> 5;
    for (int e = gwarp; e < E; e += nwarps) {
        int s = __ldg(&src[e]);
        int d = __ldg(&dst[e]);
        float norm = g_dinv[s] * g_dinv[d];
        const float4* hp = (const float4*)(h + (size_t)s * D);
        float4* op = (float4*)(out + (size_t)d * D);
#pragma unroll
        for (int i = lane; i < D / 4; i += 32) {
            float4 v = hp[i];
            v.x *= norm; v.y *= norm; v.z *= norm; v.w *= norm;
            red_add_v4(&op[i], v);
        }
    }
}

// ---------------------------------------------------------------------------
// finalize: out = (leaky_relu?)(out + b)
// ---------------------------------------------------------------------------
template <int D, bool ACT>
__global__ void finalize_kernel(float* __restrict__ out, const float* __restrict__ b, int n) {
    int idx = blockIdx.x * blockDim.x + threadIdx.x;
    int total = n * (D / 4);
    if (idx >= total) return;
    int c4 = idx % (D / 4);
    float4 bb = ((const float4*)b)[c4];
    float4 v = ((float4*)out)[idx];
    v.x += bb.x; v.y += bb.y; v.z += bb.z; v.w += bb.w;
    if (ACT) {
        v.x = v.x > 0.0f ? v.x : SLOPE * v.x;
        v.y = v.y > 0.0f ? v.y : SLOPE * v.y;
        v.z = v.z > 0.0f ? v.z : SLOPE * v.z;
        v.w = v.w > 0.0f ? v.w : SLOPE * v.w;
    }
    ((float4*)out)[idx] = v;
}

// ---------------------------------------------------------------------------
// launch
// ---------------------------------------------------------------------------
extern "C" void kernel_launch(void* const* d_in, const int* in_sizes, int n_in,
                              void* d_out, int out_size) {
    const float* x  = (const float*)d_in[0];
    const int*   ei = (const int*)d_in[1];
    const float* W1 = (const float*)d_in[2];
    const float* b1 = (const float*)d_in[3];
    const float* W2 = (const float*)d_in[4];
    const float* b2 = (const float*)d_in[5];
    const float* W3 = (const float*)d_in[6];
    const float* b3 = (const float*)d_in[7];
    float* out = (float*)d_out;

    const int N = in_sizes[0] / DH;        // 50000
    const int E = in_sizes[1] / 2;         // 800000
    const int* src = ei;
    const int* dstp = ei + E;

    float* h1 = out;
    float* h2 = out + (size_t)N * DH;
    float* lg = out + 2 * (size_t)N * DH;

    float* hbuf = nullptr;
    cudaGetSymbolAddress((void**)&hbuf, g_h);

    // --- normalization first (GEMM epilogue needs dinv) ---
    zero_deg_kernel<<<(N + 255) / 256, 256>>>(N);
    count_deg_kernel<<<(E + 255) / 256, 256>>>(dstp, E);
    dinv_kernel<<<(N + 255) / 256, 256>>>(N);

    const int scatter_blocks = (E + 7) / 8;  // 8 warps/block, 1 edge/warp
    const int grid_m = (N + 127) / 128;

    // --- layer 1: x[N,256] -> h1[N,256] ---
    {
        dim3 grid(DH / 128, grid_m);
        sgemm_fused<128, 128, 16, 8, 8><<<grid, 256>>>(x, W1, hbuf, h1, N, DH, DH);
        scatter_edges_kernel<DH><<<scatter_blocks, 256>>>(hbuf, src, dstp, h1, E);
        int tot4 = N * (DH / 4);
        finalize_kernel<DH, true><<<(tot4 + 255) / 256, 256>>>(h1, b1, N);
    }

    // --- layer 2: h1[N,256] -> h2[N,256] ---
    {
        dim3 grid(DH / 128, grid_m);
        sgemm_fused<128, 128, 16, 8, 8><<<grid, 256>>>(h1, W2, hbuf, h2, N, DH, DH);
        scatter_edges_kernel<DH><<<scatter_blocks, 256>>>(hbuf, src, dstp, h2, E);
        int tot4 = N * (DH / 4);
        finalize_kernel<DH, true><<<(tot4 + 255) / 256, 256>>>(h2, b2, N);
    }

    // --- layer 3: h2[N,256] -> logits[N,64], no activation ---
    {
        dim3 grid(DOUT / 64, grid_m);
        sgemm_fused<128, 64, 16, 8, 4><<<grid, 256>>>(h2, W3, hbuf, lg, N, DOUT, DH);
        scatter_edges_kernel<DOUT><<<scatter_blocks, 256>>>(hbuf, src, dstp, lg, E);
        int tot4 = N * (DOUT / 4);
        finalize_kernel<DOUT, false><<<(tot4 + 255) / 256, 256>>>(lg, b3, N);
    }
}

// round 6
// speedup vs baseline: 1.7974x; 1.3760x over previous
#include <cuda_runtime.h>
#include <cuda_bf16.h>

#define N_NODES 50000
#define E_MAX   800000
#define DH 256
#define DOUT 64
#define SLOPE 0.01f
#define SCAN_T 1024

// Scratch (allocation-free rule: __device__ globals)
__device__ float g_h[(size_t)N_NODES * DH];   // GEMM output per layer
__device__ int   g_deg[N_NODES];
__device__ float g_dinv[N_NODES];
__device__ int   g_row_off[N_NODES + 1];
__device__ int   g_cursor[N_NODES];
__device__ int   g_csr_src[E_MAX];

// ---------------------------------------------------------------------------
// degree / normalization / CSR build
// ---------------------------------------------------------------------------
__global__ void zero_deg_kernel(int n) {
    int i = blockIdx.x * blockDim.x + threadIdx.x;
    if (i < n) g_deg[i] = 0;
}

__global__ void count_deg_kernel(const int* __restrict__ dst, int E) {
    int i = blockIdx.x * blockDim.x + threadIdx.x;
    if (i < E) atomicAdd(&g_deg[dst[i]], 1);
}

__global__ void dinv_kernel(int n) {
    int i = blockIdx.x * blockDim.x + threadIdx.x;
    if (i < n) g_dinv[i] = rsqrtf((float)(g_deg[i] + 1));  // +1 self loop
}

// single-block exclusive scan of g_deg -> g_row_off / g_cursor
__global__ void __launch_bounds__(SCAN_T)
scan_kernel(int n) {
    __shared__ int part[SCAN_T];
    int t = threadIdx.x;
    int C = (n + SCAN_T - 1) / SCAN_T;
    int lo = t * C;
    int hi = min(lo + C, n);
    int s = 0;
    for (int i = lo; i < hi; i++) s += g_deg[i];
    part[t] = s;
    __syncthreads();
    // Hillis-Steele inclusive scan
    for (int off = 1; off < SCAN_T; off <<= 1) {
        int v = (t >= off) ? part[t - off] : 0;
        __syncthreads();
        part[t] += v;
        __syncthreads();
    }
    int base = (t == 0) ? 0 : part[t - 1];
    for (int i = lo; i < hi; i++) {
        g_row_off[i] = base;
        g_cursor[i] = base;
        base += g_deg[i];
    }
    if (t == SCAN_T - 1) g_row_off[n] = base;
}

__global__ void fill_csr_kernel(const int* __restrict__ src,
                                const int* __restrict__ dst, int E) {
    int i = blockIdx.x * blockDim.x + threadIdx.x;
    if (i < E) {
        int d = dst[i];
        int pos = atomicAdd(&g_cursor[d], 1);
        g_csr_src[pos] = src[i];
    }
}

// ---------------------------------------------------------------------------
// SGEMM: C[M,N] = A[M,K] @ W[N,K]^T  (row-major A, row-major W)
// Register-staged double buffering, BK=16, vectorized LDG/LDS/STG.
// ---------------------------------------------------------------------------
template <int BM, int BN, int BK, int TM, int TN>
__global__ void __launch_bounds__((BM / TM) * (BN / TN), 2)
sgemm_xwT(const float* __restrict__ A, const float* __restrict__ W,
          float* __restrict__ C, int M, int N, int K) {
    constexpr int THREADS = (BM / TM) * (BN / TN);
    constexpr int KV = BK / 4;
    constexpr int NA = (BM * BK) / (4 * THREADS);
    constexpr int NW = (BN * BK) / (4 * THREADS);

    __shared__ float As[BK][BM + 4];
    __shared__ float Ws[BK][BN + 4];

    const int tid = threadIdx.x;
    const int block_m = blockIdx.y * BM;
    const int block_n = blockIdx.x * BN;
    const int tcol = tid % (BN / TN);
    const int trow = tid / (BN / TN);

    float acc[TM][TN];
#pragma unroll
    for (int i = 0; i < TM; i++)
#pragma unroll
        for (int j = 0; j < TN; j++) acc[i][j] = 0.0f;

    float4 pa[NA];
    float4 pw[NW];
    const float4 fz = make_float4(0.f, 0.f, 0.f, 0.f);

#pragma unroll
    for (int i = 0; i < NA; i++) {
        int idx = tid + i * THREADS;
        int row = idx / KV, c4 = idx % KV;
        int gm = block_m + row;
        pa[i] = (gm < M) ? *(const float4*)&A[(size_t)gm * K + c4 * 4] : fz;
    }
#pragma unroll
    for (int i = 0; i < NW; i++) {
        int idx = tid + i * THREADS;
        int row = idx / KV, c4 = idx % KV;
        pw[i] = *(const float4*)&W[(size_t)(block_n + row) * K + c4 * 4];
    }
#pragma unroll
    for (int i = 0; i < NA; i++) {
        int idx = tid + i * THREADS;
        int row = idx / KV, c4 = idx % KV;
        As[c4 * 4 + 0][row] = pa[i].x;
        As[c4 * 4 + 1][row] = pa[i].y;
        As[c4 * 4 + 2][row] = pa[i].z;
        As[c4 * 4 + 3][row] = pa[i].w;
    }
#pragma unroll
    for (int i = 0; i < NW; i++) {
        int idx = tid + i * THREADS;
        int row = idx / KV, c4 = idx % KV;
        Ws[c4 * 4 + 0][row] = pw[i].x;
        Ws[c4 * 4 + 1][row] = pw[i].y;
        Ws[c4 * 4 + 2][row] = pw[i].z;
        Ws[c4 * 4 + 3][row] = pw[i].w;
    }
    __syncthreads();

    for (int k0 = BK; k0 < K; k0 += BK) {
#pragma unroll
        for (int i = 0; i < NA; i++) {
            int idx = tid + i * THREADS;
            int row = idx / KV, c4 = idx % KV;
            int gm = block_m + row;
            pa[i] = (gm < M) ? *(const float4*)&A[(size_t)gm * K + k0 + c4 * 4] : fz;
        }
#pragma unroll
        for (int i = 0; i < NW; i++) {
            int idx = tid + i * THREADS;
            int row = idx / KV, c4 = idx % KV;
            pw[i] = *(const float4*)&W[(size_t)(block_n + row) * K + k0 + c4 * 4];
        }

#pragma unroll
        for (int k = 0; k < BK; k++) {
            float ra[TM], rb[TN];
#pragma unroll
            for (int v = 0; v < TM / 4; v++)
                *(float4*)&ra[v * 4] = *(const float4*)&As[k][trow * TM + v * 4];
#pragma unroll
            for (int v = 0; v < TN / 4; v++)
                *(float4*)&rb[v * 4] = *(const float4*)&Ws[k][tcol * TN + v * 4];
#pragma unroll
            for (int i = 0; i < TM; i++)
#pragma unroll
                for (int j = 0; j < TN; j++) acc[i][j] = fmaf(ra[i], rb[j], acc[i][j]);
        }
        __syncthreads();

#pragma unroll
        for (int i = 0; i < NA; i++) {
            int idx = tid + i * THREADS;
            int row = idx / KV, c4 = idx % KV;
            As[c4 * 4 + 0][row] = pa[i].x;
            As[c4 * 4 + 1][row] = pa[i].y;
            As[c4 * 4 + 2][row] = pa[i].z;
            As[c4 * 4 + 3][row] = pa[i].w;
        }
#pragma unroll
        for (int i = 0; i < NW; i++) {
            int idx = tid + i * THREADS;
            int row = idx / KV, c4 = idx % KV;
            Ws[c4 * 4 + 0][row] = pw[i].x;
            Ws[c4 * 4 + 1][row] = pw[i].y;
            Ws[c4 * 4 + 2][row] = pw[i].z;
            Ws[c4 * 4 + 3][row] = pw[i].w;
        }
        __syncthreads();
    }

#pragma unroll
    for (int k = 0; k < BK; k++) {
        float ra[TM], rb[TN];
#pragma unroll
        for (int v = 0; v < TM / 4; v++)
            *(float4*)&ra[v * 4] = *(const float4*)&As[k][trow * TM + v * 4];
#pragma unroll
        for (int v = 0; v < TN / 4; v++)
            *(float4*)&rb[v * 4] = *(const float4*)&Ws[k][tcol * TN + v * 4];
#pragma unroll
        for (int i = 0; i < TM; i++)
#pragma unroll
            for (int j = 0; j < TN; j++) acc[i][j] = fmaf(ra[i], rb[j], acc[i][j]);
    }

#pragma unroll
    for (int i = 0; i < TM; i++) {
        int gm = block_m + trow * TM + i;
        if (gm < M) {
#pragma unroll
            for (int v = 0; v < TN / 4; v++) {
                size_t off = (size_t)gm * N + block_n + tcol * TN + v * 4;
                *(float4*)&C[off] = make_float4(acc[i][v * 4 + 0], acc[i][v * 4 + 1],
                                                acc[i][v * 4 + 2], acc[i][v * 4 + 3]);
            }
        }
    }
}

// ---------------------------------------------------------------------------
// CSR gather, fully fused: one warp per node.
// out[d] = act( b + dinv[d]^2*h[d] + sum_{e in row(d)} dinv[src]*dinv[d]*h[src] )
// ---------------------------------------------------------------------------
template <int D, bool ACT>
__global__ void gather_csr_kernel(const float* __restrict__ h,
                                  const float* __restrict__ b,
                                  float* __restrict__ out, int N) {
    constexpr int VEC = D / 4;                 // float4 per row
    constexpr int PER = (VEC + 31) / 32;       // float4 per lane
    int gw = (blockIdx.x * blockDim.x + threadIdx.x) >> 5;
    int lane = threadIdx.x & 31;
    if (gw >= N) return;

    float dd = g_dinv[gw];
    float w = dd * dd;
    const float4* hd = (const float4*)(h + (size_t)gw * D);

    float4 acc[PER];
#pragma unroll
    for (int j = 0; j < PER; j++) {
        int idx = lane + j * 32;
        if (idx < VEC) {
            float4 v = hd[idx];
            acc[j] = make_float4(v.x * w, v.y * w, v.z * w, v.w * w);
        } else {
            acc[j] = make_float4(0.f, 0.f, 0.f, 0.f);
        }
    }

    int e0 = g_row_off[gw];
    int e1 = g_row_off[gw + 1];
    for (int e = e0; e < e1; e++) {
        int s = __ldg(&g_csr_src[e]);
        float norm = g_dinv[s] * dd;
        const float4* hs = (const float4*)(h + (size_t)s * D);
#pragma unroll
        for (int j = 0; j < PER; j++) {
            int idx = lane + j * 32;
            if (idx < VEC) {
                float4 v = hs[idx];
                acc[j].x = fmaf(norm, v.x, acc[j].x);
                acc[j].y = fmaf(norm, v.y, acc[j].y);
                acc[j].z = fmaf(norm, v.z, acc[j].z);
                acc[j].w = fmaf(norm, v.w, acc[j].w);
            }
        }
    }

    const float4* bb = (const float4*)b;
    float4* op = (float4*)(out + (size_t)gw * D);
#pragma unroll
    for (int j = 0; j < PER; j++) {
        int idx = lane + j * 32;
        if (idx < VEC) {
            float4 v = acc[j];
            float4 B = bb[idx];
            v.x += B.x; v.y += B.y; v.z += B.z; v.w += B.w;
            if (ACT) {
                v.x = v.x > 0.0f ? v.x : SLOPE * v.x;
                v.y = v.y > 0.0f ? v.y : SLOPE * v.y;
                v.z = v.z > 0.0f ? v.z : SLOPE * v.z;
                v.w = v.w > 0.0f ? v.w : SLOPE * v.w;
            }
            op[idx] = v;
        }
    }
}

// ---------------------------------------------------------------------------
// launch
// ---------------------------------------------------------------------------
extern "C" void kernel_launch(void* const* d_in, const int* in_sizes, int n_in,
                              void* d_out, int out_size) {
    const float* x  = (const float*)d_in[0];
    const int*   ei = (const int*)d_in[1];
    const float* W1 = (const float*)d_in[2];
    const float* b1 = (const float*)d_in[3];
    const float* W2 = (const float*)d_in[4];
    const float* b2 = (const float*)d_in[5];
    const float* W3 = (const float*)d_in[6];
    const float* b3 = (const float*)d_in[7];
    float* out = (float*)d_out;

    const int N = in_sizes[0] / DH;        // 50000
    const int E = in_sizes[1] / 2;         // 800000
    const int* src = ei;
    const int* dstp = ei + E;

    float* h1 = out;
    float* h2 = out + (size_t)N * DH;
    float* lg = out + 2 * (size_t)N * DH;

    float* hbuf = nullptr;
    cudaGetSymbolAddress((void**)&hbuf, g_h);

    // --- degree / dinv / CSR (edge structure shared across the 3 layers) ---
    zero_deg_kernel<<<(N + 255) / 256, 256>>>(N);
    count_deg_kernel<<<(E + 255) / 256, 256>>>(dstp, E);
    dinv_kernel<<<(N + 255) / 256, 256>>>(N);
    scan_kernel<<<1, SCAN_T>>>(N);
    fill_csr_kernel<<<(E + 255) / 256, 256>>>(src, dstp, E);

    const int gather_blocks = (N + 7) / 8;   // 8 warps/block, 1 node/warp
    const int grid_m = (N + 127) / 128;

    // --- layer 1: x[N,256] -> h1[N,256] ---
    {
        dim3 grid(DH / 128, grid_m);
        sgemm_xwT<128, 128, 16, 8, 8><<<grid, 256>>>(x, W1, hbuf, N, DH, DH);
        gather_csr_kernel<DH, true><<<gather_blocks, 256>>>(hbuf, b1, h1, N);
    }

    // --- layer 2: h1[N,256] -> h2[N,256] ---
    {
        dim3 grid(DH / 128, grid_m);
        sgemm_xwT<128, 128, 16, 8, 8><<<grid, 256>>>(h1, W2, hbuf, N, DH, DH);
        gather_csr_kernel<DH, true><<<gather_blocks, 256>>>(hbuf, b2, h2, N);
    }

    // --- layer 3: h2[N,256] -> logits[N,64], no activation ---
    {
        dim3 grid(DOUT / 64, grid_m);
        sgemm_xwT<128, 64, 16, 8, 4><<<grid, 256>>>(h2, W3, hbuf, N, DOUT, DH);
        gather_csr_kernel<DOUT, false><<<gather_blocks, 256>>>(hbuf, b3, lg, N);
    }
}

// round 10
// speedup vs baseline: 2.7168x; 1.5115x over previous
#include <cuda_runtime.h>
#include <cuda_bf16.h>
#include <cstdint>

#define N_NODES 50000
#define E_MAX   800000
#define DH 256
#define DOUT 64
#define SLOPE 0.01f

// ---------------------------------------------------------------------------
// Scratch (allocation-free rule: __device__ globals)
// ---------------------------------------------------------------------------
__device__ float g_h[(size_t)N_NODES * DH];   // GEMM output per layer
__device__ int   g_deg[N_NODES];
__device__ float g_dinv[N_NODES];
__device__ int   g_row_off[N_NODES + 1];
__device__ int   g_cursor[N_NODES];
__device__ int   g_csr_src[E_MAX];
__device__ int   g_bsum[256];
__device__ int   g_boff[256];
// bf16 hi/lo weight splits, plain row-major [NOUT][256]
__device__ unsigned short g_W1hi[DH * DH], g_W1lo[DH * DH];
__device__ unsigned short g_W2hi[DH * DH], g_W2lo[DH * DH];
__device__ unsigned short g_W3hi[DOUT * DH], g_W3lo[DOUT * DH];

__device__ __forceinline__ uint32_t smem_to_u32(const void* p) {
    uint32_t a;
    asm("{ .reg .u64 t; cvta.to.shared.u64 t, %1; cvt.u32.u64 %0, t; }" : "=r"(a) : "l"(p));
    return a;
}
__device__ __forceinline__ unsigned short bfbits(float f) {
    __nv_bfloat16 b = __float2bfloat16(f);
    return *reinterpret_cast<unsigned short*>(&b);
}
__device__ __forceinline__ float bf2f(unsigned short u) {
    __nv_bfloat16 b = *reinterpret_cast<__nv_bfloat16*>(&u);
    return __bfloat162float(b);
}

#define LDSM_X4(R, ADDR) \
    asm volatile("ldmatrix.sync.aligned.m8n8.x4.shared.b16 {%0,%1,%2,%3}, [%4];" \
                 : "=r"((R)[0]), "=r"((R)[1]), "=r"((R)[2]), "=r"((R)[3]) : "r"(ADDR))

#define MMA_BF16(C, A, B0, B1) \
    asm volatile("mma.sync.aligned.m16n8k16.row.col.f32.bf16.bf16.f32 " \
                 "{%0,%1,%2,%3}, {%4,%5,%6,%7}, {%8,%9}, {%0,%1,%2,%3};" \
                 : "+f"((C)[0]), "+f"((C)[1]), "+f"((C)[2]), "+f"((C)[3]) \
                 : "r"((A)[0]), "r"((A)[1]), "r"((A)[2]), "r"((A)[3]), "r"(B0), "r"(B1))

// ---------------------------------------------------------------------------
// degree / normalization / CSR build (parallel scan)
// ---------------------------------------------------------------------------
__global__ void zero_deg_kernel(int n) {
    int i = blockIdx.x * blockDim.x + threadIdx.x;
    if (i < n) g_deg[i] = 0;
}
__global__ void count_deg_kernel(const int* __restrict__ dst, int E) {
    int i = blockIdx.x * blockDim.x + threadIdx.x;
    if (i < E) atomicAdd(&g_deg[dst[i]], 1);
}
__global__ void dinv_kernel(int n) {
    int i = blockIdx.x * blockDim.x + threadIdx.x;
    if (i < n) g_dinv[i] = rsqrtf((float)(g_deg[i] + 1));
}
__global__ void block_sum_kernel(int n) {
    __shared__ int s[256];
    int i = blockIdx.x * 256 + threadIdx.x;
    s[threadIdx.x] = (i < n) ? g_deg[i] : 0;
    __syncthreads();
    for (int o = 128; o > 0; o >>= 1) {
        if (threadIdx.x < o) s[threadIdx.x] += s[threadIdx.x + o];
        __syncthreads();
    }
    if (threadIdx.x == 0) g_bsum[blockIdx.x] = s[0];
}
__global__ void scan_bsums_kernel(int nb) {
    __shared__ int s[256];
    int t = threadIdx.x;
    s[t] = (t < nb) ? g_bsum[t] : 0;
    __syncthreads();
    for (int o = 1; o < 256; o <<= 1) {
        int v = (t >= o) ? s[t - o] : 0;
        __syncthreads();
        s[t] += v;
        __syncthreads();
    }
    if (t < nb) g_boff[t] = (t == 0) ? 0 : s[t - 1];
}
__global__ void fill_offsets_kernel(int n, int E) {
    __shared__ int s[256];
    int t = threadIdx.x;
    int i = blockIdx.x * 256 + t;
    int d = (i < n) ? g_deg[i] : 0;
    s[t] = d;
    __syncthreads();
    for (int o = 1; o < 256; o <<= 1) {
        int v = (t >= o) ? s[t - o] : 0;
        __syncthreads();
        s[t] += v;
        __syncthreads();
    }
    int excl = s[t] - d + g_boff[blockIdx.x];
    if (i < n) { g_row_off[i] = excl; g_cursor[i] = excl; }
    if (i == n - 1) g_row_off[n] = E;
}
__global__ void fill_csr_kernel(const int* __restrict__ src,
                                const int* __restrict__ dst, int E) {
    int i = blockIdx.x * blockDim.x + threadIdx.x;
    if (i < E) {
        int d = dst[i];
        int pos = atomicAdd(&g_cursor[d], 1);
        g_csr_src[pos] = src[i];
    }
}

// ---------------------------------------------------------------------------
// Weight prep: fp32 -> bf16 hi/lo, plain row-major
// ---------------------------------------------------------------------------
__global__ void prep_w_kernel(const float* __restrict__ W,
                              unsigned short* __restrict__ Whi,
                              unsigned short* __restrict__ Wlo, int total) {
    int idx = blockIdx.x * blockDim.x + threadIdx.x;
    if (idx >= total) return;
    float w = W[idx];
    unsigned short h = bfbits(w);
    Whi[idx] = h;
    Wlo[idx] = bfbits(w - bf2f(h));
}

// ---------------------------------------------------------------------------
// bf16-split MMA GEMM: C[M,NOUT] = A[M,256] @ W[NOUT,256]^T, fp32 accum.
// mma.sync.m16n8k16 (3 passes: hi*hi + hi*lo + lo*hi).
// BM=128, BK=32, 256 threads (8 warps, warp tile WMx32), double-buffered SMEM.
// ---------------------------------------------------------------------------
template <int BN>
__global__ void __launch_bounds__(256)
gemm_mma(const float* __restrict__ A,
         const unsigned short* __restrict__ Whi,
         const unsigned short* __restrict__ Wlo,
         float* __restrict__ C, int M, int NOUT) {
    constexpr int BM = 128, BK = 32, KD = 256;
    constexpr int NTILES = KD / BK;                  // 8
    constexpr int WARPS_N = BN / 32;
    constexpr int WARPS_M = 8 / WARPS_N;
    constexpr int WM = BM / WARPS_M;
    constexpr int MT = WM / 16;
    constexpr int SA = 40;                           // padded row stride (bf16 units)
    constexpr int ABYTES = BM * SA * 2;              // 10240
    constexpr int BBYTES = BN * SA * 2;
    constexpr int STAGE = 2 * ABYTES + 2 * BBYTES;
    constexpr int NBL = BN / 32;                     // uint2 B-loads per thread per matrix

    extern __shared__ char smem_raw[];
    const uint32_t sbase = smem_to_u32(smem_raw);

    const int tid = threadIdx.x;
    const int lane = tid & 31;
    const int wid = tid >> 5;
    const int warp_n = wid % WARPS_N;
    const int warp_m = wid / WARPS_N;
    const int l16 = lane & 15;
    const int lg = lane >> 4;
    const int block_m = blockIdx.x * BM;
    const int block_n = blockIdx.y * BN;

    float c[MT][4][4];
#pragma unroll
    for (int i = 0; i < MT; i++)
#pragma unroll
        for (int j = 0; j < 4; j++)
#pragma unroll
            for (int q = 0; q < 4; q++) c[i][j][q] = 0.0f;

    // staging registers
    float4 areg[4];
    uint2 bhreg[NBL], blreg[NBL];

    // per-thread load indices
    const int a_r0 = tid >> 3;        // +32*i
    const int a_c4 = tid & 7;

    auto load_global = [&](int t) {
        int k8 = t * 8;               // float4 / uint2(4bf16) offset along K
#pragma unroll
        for (int i = 0; i < 4; i++) {
            int row = a_r0 + 32 * i;
            int gm = block_m + row;
            int rowc = gm < M ? gm : M - 1;
            areg[i] = __ldg((const float4*)A + (size_t)rowc * 64 + k8 + a_c4);
        }
#pragma unroll
        for (int j = 0; j < NBL; j++) {
            int flat = tid + 256 * j;
            int row = flat >> 3, c2 = flat & 7;
            size_t gidx = (size_t)(block_n + row) * 64 + k8 + c2;
            bhreg[j] = __ldg((const uint2*)Whi + gidx);
            blreg[j] = __ldg((const uint2*)Wlo + gidx);
        }
    };

    auto store_stage = [&](int st) {
        char* ah = smem_raw + st * STAGE;
        char* al = ah + ABYTES;
        char* bh = ah + 2 * ABYTES;
        char* bl = bh + BBYTES;
#pragma unroll
        for (int i = 0; i < 4; i++) {
            int row = a_r0 + 32 * i;
            float4 f = areg[i];
            unsigned short hx = bfbits(f.x), hy = bfbits(f.y);
            unsigned short hz = bfbits(f.z), hw = bfbits(f.w);
            unsigned short lx = bfbits(f.x - bf2f(hx));
            unsigned short ly = bfbits(f.y - bf2f(hy));
            unsigned short lz = bfbits(f.z - bf2f(hz));
            unsigned short lw = bfbits(f.w - bf2f(hw));
            uint2 hv = make_uint2(((uint32_t)hy << 16) | hx, ((uint32_t)hw << 16) | hz);
            uint2 lv = make_uint2(((uint32_t)ly << 16) | lx, ((uint32_t)lw << 16) | lz);
            uint32_t off = (uint32_t)row * (SA * 2) + a_c4 * 8;
            *(uint2*)(ah + off) = hv;
            *(uint2*)(al + off) = lv;
        }
#pragma unroll
        for (int j = 0; j < NBL; j++) {
            int flat = tid + 256 * j;
            int row = flat >> 3, c2 = flat & 7;
            uint32_t off = (uint32_t)row * (SA * 2) + c2 * 8;
            *(uint2*)(bh + off) = bhreg[j];
            *(uint2*)(bl + off) = blreg[j];
        }
    };

    // prologue
    load_global(0);
    store_stage(0);
    __syncthreads();

    for (int t = 0; t < NTILES; t++) {
        int cur = t & 1;
        if (t + 1 < NTILES) load_global(t + 1);

        uint32_t ahi = sbase + cur * STAGE;
        uint32_t alo = ahi + ABYTES;
        uint32_t bhi = ahi + 2 * ABYTES;
        uint32_t blo = bhi + BBYTES;

#pragma unroll
        for (int kb = 0; kb < 2; kb++) {
            uint32_t koff = (uint32_t)(kb * 16 + lg * 8) * 2;
            // B fragments: 2 x4 loads cover 32 n-cols (4 n8 tiles)
            uint32_t bhf[2][4], blf[2][4];
#pragma unroll
            for (int ntp = 0; ntp < 2; ntp++) {
                uint32_t roff = (uint32_t)(warp_n * 32 + ntp * 16 + l16) * (SA * 2) + koff;
                LDSM_X4(bhf[ntp], bhi + roff);
                LDSM_X4(blf[ntp], blo + roff);
            }
#pragma unroll
            for (int mt = 0; mt < MT; mt++) {
                uint32_t roff = (uint32_t)(warp_m * WM + mt * 16 + l16) * (SA * 2) + koff;
                uint32_t ah[4], al[4];
                LDSM_X4(ah, ahi + roff);
                LDSM_X4(al, alo + roff);
#pragma unroll
                for (int ntp = 0; ntp < 2; ntp++) {
#pragma unroll
                    for (int sub = 0; sub < 2; sub++) {
                        int nt = ntp * 2 + sub;
                        uint32_t b0h = bhf[ntp][sub], b1h = bhf[ntp][sub + 2];
                        uint32_t b0l = blf[ntp][sub], b1l = blf[ntp][sub + 2];
                        MMA_BF16(c[mt][nt], ah, b0h, b1h);
                        MMA_BF16(c[mt][nt], ah, b0l, b1l);
                        MMA_BF16(c[mt][nt], al, b0h, b1h);
                    }
                }
            }
        }

        if (t + 1 < NTILES) {
            store_stage((t + 1) & 1);
            __syncthreads();
        }
    }

    // epilogue: fragment -> gmem (float2 per quad)
#pragma unroll
    for (int mt = 0; mt < MT; mt++) {
#pragma unroll
        for (int nt = 0; nt < 4; nt++) {
            int r0 = block_m + warp_m * WM + mt * 16 + (lane >> 2);
            int col = block_n + warp_n * 32 + nt * 8 + (lane & 3) * 2;
            if (r0 < M)
                *(float2*)&C[(size_t)r0 * NOUT + col] = make_float2(c[mt][nt][0], c[mt][nt][1]);
            int r1 = r0 + 8;
            if (r1 < M)
                *(float2*)&C[(size_t)r1 * NOUT + col] = make_float2(c[mt][nt][2], c[mt][nt][3]);
        }
    }
}

// ---------------------------------------------------------------------------
// CSR gather, fully fused: one warp per node.
// ---------------------------------------------------------------------------
template <int D, bool ACT>
__global__ void gather_csr_kernel(const float* __restrict__ h,
                                  const float* __restrict__ b,
                                  float* __restrict__ out, int N) {
    constexpr int VEC = D / 4;
    constexpr int PER = (VEC + 31) / 32;
    int gw = (blockIdx.x * blockDim.x + threadIdx.x) >> 5;
    int lane = threadIdx.x & 31;
    if (gw >= N) return;

    float dd = g_dinv[gw];
    float w = dd * dd;
    const float4* hd = (const float4*)(h + (size_t)gw * D);

    float4 acc[PER];
#pragma unroll
    for (int j = 0; j < PER; j++) {
        int idx = lane + j * 32;
        if (idx < VEC) {
            float4 v = hd[idx];
            acc[j] = make_float4(v.x * w, v.y * w, v.z * w, v.w * w);
        } else acc[j] = make_float4(0.f, 0.f, 0.f, 0.f);
    }

    int e0 = g_row_off[gw];
    int e1 = g_row_off[gw + 1];
    for (int e = e0; e < e1; e++) {
        int s = __ldg(&g_csr_src[e]);
        float norm = g_dinv[s] * dd;
        const float4* hs = (const float4*)(h + (size_t)s * D);
#pragma unroll
        for (int j = 0; j < PER; j++) {
            int idx = lane + j * 32;
            if (idx < VEC) {
                float4 v = hs[idx];
                acc[j].x = fmaf(norm, v.x, acc[j].x);
                acc[j].y = fmaf(norm, v.y, acc[j].y);
                acc[j].z = fmaf(norm, v.z, acc[j].z);
                acc[j].w = fmaf(norm, v.w, acc[j].w);
            }
        }
    }

    const float4* bb = (const float4*)b;
    float4* op = (float4*)(out + (size_t)gw * D);
#pragma unroll
    for (int j = 0; j < PER; j++) {
        int idx = lane + j * 32;
        if (idx < VEC) {
            float4 v = acc[j];
            float4 B = bb[idx];
            v.x += B.x; v.y += B.y; v.z += B.z; v.w += B.w;
            if (ACT) {
                v.x = v.x > 0.0f ? v.x : SLOPE * v.x;
                v.y = v.y > 0.0f ? v.y : SLOPE * v.y;
                v.z = v.z > 0.0f ? v.z : SLOPE * v.z;
                v.w = v.w > 0.0f ? v.w : SLOPE * v.w;
            }
            op[idx] = v;
        }
    }
}

// ---------------------------------------------------------------------------
// launch
// ---------------------------------------------------------------------------
extern "C" void kernel_launch(void* const* d_in, const int* in_sizes, int n_in,
                              void* d_out, int out_size) {
    const float* x  = (const float*)d_in[0];
    const int*   ei = (const int*)d_in[1];
    const float* W1 = (const float*)d_in[2];
    const float* b1 = (const float*)d_in[3];
    const float* W2 = (const float*)d_in[4];
    const float* b2 = (const float*)d_in[5];
    const float* W3 = (const float*)d_in[6];
    const float* b3 = (const float*)d_in[7];
    float* out = (float*)d_out;

    const int N = in_sizes[0] / DH;
    const int E = in_sizes[1] / 2;
    const int* src = ei;
    const int* dstp = ei + E;

    float* h1 = out;
    float* h2 = out + (size_t)N * DH;
    float* lg = out + 2 * (size_t)N * DH;

    float* hbuf = nullptr;
    cudaGetSymbolAddress((void**)&hbuf, g_h);
    unsigned short *w1h, *w1l, *w2h, *w2l, *w3h, *w3l;
    cudaGetSymbolAddress((void**)&w1h, g_W1hi); cudaGetSymbolAddress((void**)&w1l, g_W1lo);
    cudaGetSymbolAddress((void**)&w2h, g_W2hi); cudaGetSymbolAddress((void**)&w2l, g_W2lo);
    cudaGetSymbolAddress((void**)&w3h, g_W3hi); cudaGetSymbolAddress((void**)&w3l, g_W3lo);

    // dynamic smem: double-buffered stage = 2*(A hi/lo) + 2*(B hi/lo)
    const int SMEM128 = 2 * (2 * 10240 + 2 * 10240);  // 81920
    const int SMEM64  = 2 * (2 * 10240 + 2 * 5120);   // 61440
    cudaFuncSetAttribute(gemm_mma<128>, cudaFuncAttributeMaxDynamicSharedMemorySize, SMEM128);
    cudaFuncSetAttribute(gemm_mma<64>,  cudaFuncAttributeMaxDynamicSharedMemorySize, SMEM64);

    // --- weight prep ---
    prep_w_kernel<<<(DH * DH + 255) / 256, 256>>>(W1, w1h, w1l, DH * DH);
    prep_w_kernel<<<(DH * DH + 255) / 256, 256>>>(W2, w2h, w2l, DH * DH);
    prep_w_kernel<<<(DOUT * DH + 255) / 256, 256>>>(W3, w3h, w3l, DOUT * DH);

    // --- degree / dinv / CSR ---
    const int NB = (N + 255) / 256;
    zero_deg_kernel<<<NB, 256>>>(N);
    count_deg_kernel<<<(E + 255) / 256, 256>>>(dstp, E);
    dinv_kernel<<<NB, 256>>>(N);
    block_sum_kernel<<<NB, 256>>>(N);
    scan_bsums_kernel<<<1, 256>>>(NB);
    fill_offsets_kernel<<<NB, 256>>>(N, E);
    fill_csr_kernel<<<(E + 255) / 256, 256>>>(src, dstp, E);

    const int gather_blocks = (N + 7) / 8;
    const int tiles_m = (N + 127) / 128;

    // --- layer 1 ---
    gemm_mma<128><<<dim3(tiles_m, DH / 128), 256, SMEM128>>>(x, w1h, w1l, hbuf, N, DH);
    gather_csr_kernel<DH, true><<<gather_blocks, 256>>>(hbuf, b1, h1, N);

    // --- layer 2 ---
    gemm_mma<128><<<dim3(tiles_m, DH / 128), 256, SMEM128>>>(h1, w2h, w2l, hbuf, N, DH);
    gather_csr_kernel<DH, true><<<gather_blocks, 256>>>(hbuf, b2, h2, N);

    // --- layer 3 ---
    gemm_mma<64><<<dim3(tiles_m, DOUT / 64), 256, SMEM64>>>(h2, w3h, w3l, hbuf, N, DOUT);
    gather_csr_kernel<DOUT, false><<<gather_blocks, 256>>>(hbuf, b3, lg, N);
}

// round 11
// speedup vs baseline: 3.6311x; 1.3365x over previous
#include <cuda_runtime.h>
#include <cuda_bf16.h>
#include <cstdint>

#define N_NODES 50000
#define E_MAX   800000
#define DH 256
#define DOUT 64
#define SLOPE 0.01f

// ---------------------------------------------------------------------------
// Scratch (allocation-free rule: __device__ globals)
// ---------------------------------------------------------------------------
__device__ float g_h[(size_t)N_NODES * DH];   // GEMM output per layer
__device__ int   g_deg[N_NODES];
__device__ float g_dinv[N_NODES];
__device__ int   g_row_off[N_NODES + 1];
__device__ int   g_cursor[N_NODES];
__device__ int   g_csr_src[E_MAX];
__device__ int   g_bsum[256];
__device__ int   g_boff[256];

__device__ __forceinline__ uint32_t smem_to_u32(const void* p) {
    uint32_t a;
    asm("{ .reg .u64 t; cvta.to.shared.u64 t, %1; cvt.u32.u64 %0, t; }" : "=r"(a) : "l"(p));
    return a;
}
__device__ __forceinline__ uint32_t f2tf32(float f) {
    uint32_t o;
    asm("cvt.rna.tf32.f32 %0, %1;" : "=r"(o) : "f"(f));
    return o;
}

#define LDSM_X4(R, ADDR) \
    asm volatile("ldmatrix.sync.aligned.m8n8.x4.shared.b16 {%0,%1,%2,%3}, [%4];" \
                 : "=r"((R)[0]), "=r"((R)[1]), "=r"((R)[2]), "=r"((R)[3]) : "r"(ADDR))

#define MMA_TF32(C, A, B0, B1) \
    asm volatile("mma.sync.aligned.m16n8k8.row.col.f32.tf32.tf32.f32 " \
                 "{%0,%1,%2,%3}, {%4,%5,%6,%7}, {%8,%9}, {%0,%1,%2,%3};" \
                 : "+f"((C)[0]), "+f"((C)[1]), "+f"((C)[2]), "+f"((C)[3]) \
                 : "r"((A)[0]), "r"((A)[1]), "r"((A)[2]), "r"((A)[3]), "r"(B0), "r"(B1))

// ---------------------------------------------------------------------------
// degree / normalization / CSR build (parallel scan)
// ---------------------------------------------------------------------------
__global__ void count_deg_kernel(const int* __restrict__ dst, int E) {
    int i = blockIdx.x * blockDim.x + threadIdx.x;
    if (i < E) atomicAdd(&g_deg[dst[i]], 1);
}
// fused: dinv + per-block degree sums
__global__ void dinv_blocksum_kernel(int n) {
    __shared__ int s[256];
    int i = blockIdx.x * 256 + threadIdx.x;
    int d = (i < n) ? g_deg[i] : 0;
    if (i < n) g_dinv[i] = rsqrtf((float)(d + 1));
    s[threadIdx.x] = d;
    __syncthreads();
    for (int o = 128; o > 0; o >>= 1) {
        if (threadIdx.x < o) s[threadIdx.x] += s[threadIdx.x + o];
        __syncthreads();
    }
    if (threadIdx.x == 0) g_bsum[blockIdx.x] = s[0];
}
__global__ void scan_bsums_kernel(int nb) {
    __shared__ int s[256];
    int t = threadIdx.x;
    s[t] = (t < nb) ? g_bsum[t] : 0;
    __syncthreads();
    for (int o = 1; o < 256; o <<= 1) {
        int v = (t >= o) ? s[t - o] : 0;
        __syncthreads();
        s[t] += v;
        __syncthreads();
    }
    if (t < nb) g_boff[t] = (t == 0) ? 0 : s[t - 1];
}
__global__ void fill_offsets_kernel(int n, int E) {
    __shared__ int s[256];
    int t = threadIdx.x;
    int i = blockIdx.x * 256 + t;
    int d = (i < n) ? g_deg[i] : 0;
    s[t] = d;
    __syncthreads();
    for (int o = 1; o < 256; o <<= 1) {
        int v = (t >= o) ? s[t - o] : 0;
        __syncthreads();
        s[t] += v;
        __syncthreads();
    }
    int excl = s[t] - d + g_boff[blockIdx.x];
    if (i < n) { g_row_off[i] = excl; g_cursor[i] = excl; }
    if (i == n - 1) g_row_off[n] = E;
}
__global__ void fill_csr_kernel(const int* __restrict__ src,
                                const int* __restrict__ dst, int E) {
    int i = blockIdx.x * blockDim.x + threadIdx.x;
    if (i < E) {
        int d = dst[i];
        int pos = atomicAdd(&g_cursor[d], 1);
        g_csr_src[pos] = src[i];
    }
}

// ---------------------------------------------------------------------------
// Single-pass TF32 MMA GEMM: C[M,NOUT] = A[M,256] @ W[NOUT,256]^T, fp32 accum.
// mma.sync.m16n8k8.tf32. BM=128, BK=32, 256 threads (8 warps, warp n-width 32),
// double-buffered SMEM (stride 36 floats — ldmatrix + STS.128 conflict-free).
// TF32 fragment layouts load directly via ldmatrix.x4 on fp32-as-b16x2 tiles.
// ---------------------------------------------------------------------------
template <int BN>
__global__ void __launch_bounds__(256)
gemm_tf32(const float* __restrict__ A, const float* __restrict__ W,
          float* __restrict__ C, int M, int NOUT) {
    constexpr int BM = 128, KD = 256;
    constexpr int NTILES = KD / 32;                  // 8 BK-tiles
    constexpr int WARPS_N = BN / 32;
    constexpr int WARPS_M = 8 / WARPS_N;
    constexpr int WM = BM / WARPS_M;
    constexpr int MT = WM / 16;
    constexpr int SA = 36;                           // padded stride (floats)
    constexpr int ABYTES = BM * SA * 4;              // 18432
    constexpr int BBYTES = BN * SA * 4;
    constexpr int STAGE = ABYTES + BBYTES;
    constexpr int NBL = BN / 32;                     // B float4 loads / thread

    extern __shared__ char smem_raw[];
    const uint32_t sbase = smem_to_u32(smem_raw);

    const int tid = threadIdx.x;
    const int lane = tid & 31;
    const int wid = tid >> 5;
    const int warp_n = wid % WARPS_N;
    const int warp_m = wid / WARPS_N;
    const int block_m = blockIdx.x * BM;
    const int block_n = blockIdx.y * BN;

    float c[MT][4][4];
#pragma unroll
    for (int i = 0; i < MT; i++)
#pragma unroll
        for (int j = 0; j < 4; j++)
#pragma unroll
            for (int q = 0; q < 4; q++) c[i][j][q] = 0.0f;

    // ldmatrix lane addressing (within tile, in floats)
    const int a_lrow = lane & 15;            // row offset
    const int a_lcol = (lane >> 4) * 4;      // col offset
    const int b_lrow = (lane & 7) + ((lane >> 4) * 8);
    const int b_lcol = ((lane >> 3) & 1) * 4;

    // staging registers + per-thread global-load indices
    float4 areg[4];
    float4 breg[NBL];
    const int a_r0 = tid >> 3;               // + 32*i
    const int a_c4 = tid & 7;

    auto load_global = [&](int t) {
        int k8 = t * 8;
#pragma unroll
        for (int i = 0; i < 4; i++) {
            int gm = block_m + a_r0 + 32 * i;
            int rowc = gm < M ? gm : M - 1;
            areg[i] = __ldg((const float4*)A + (size_t)rowc * 64 + k8 + a_c4);
        }
#pragma unroll
        for (int j = 0; j < NBL; j++) {
            int flat = tid + 256 * j;
            int row = flat >> 3, c4 = flat & 7;
            breg[j] = __ldg((const float4*)W + (size_t)(block_n + row) * 64 + k8 + c4);
        }
    };

    auto store_stage = [&](int st) {
        uint32_t* ab = (uint32_t*)(smem_raw + st * STAGE);
        uint32_t* bb = (uint32_t*)(smem_raw + st * STAGE + ABYTES);
#pragma unroll
        for (int i = 0; i < 4; i++) {
            uint32_t off = (uint32_t)(a_r0 + 32 * i) * SA + a_c4 * 4;
            float4 f = areg[i];
            *(uint4*)(ab + off) = make_uint4(f2tf32(f.x), f2tf32(f.y), f2tf32(f.z), f2tf32(f.w));
        }
#pragma unroll
        for (int j = 0; j < NBL; j++) {
            int flat = tid + 256 * j;
            uint32_t off = (uint32_t)(flat >> 3) * SA + (flat & 7) * 4;
            float4 f = breg[j];
            *(uint4*)(bb + off) = make_uint4(f2tf32(f.x), f2tf32(f.y), f2tf32(f.z), f2tf32(f.w));
        }
    };

    load_global(0);
    store_stage(0);
    __syncthreads();

    for (int t = 0; t < NTILES; t++) {
        int cur = t & 1;
        if (t + 1 < NTILES) load_global(t + 1);

        uint32_t abase = sbase + cur * STAGE;
        uint32_t bbase = abase + ABYTES;

#pragma unroll
        for (int kb = 0; kb < 4; kb++) {
            int koff = kb * 8;
            // B fragments: 2 x4 ldmatrix cover 4 n8-tiles (b0,b1 each)
            uint32_t bf[2][4];
#pragma unroll
            for (int ntp = 0; ntp < 2; ntp++) {
                uint32_t addr = bbase + ((uint32_t)(warp_n * 32 + ntp * 16 + b_lrow) * SA +
                                         koff + b_lcol) * 4;
                LDSM_X4(bf[ntp], addr);
            }
#pragma unroll
            for (int mt = 0; mt < MT; mt++) {
                uint32_t af[4];
                uint32_t addr = abase + ((uint32_t)(warp_m * WM + mt * 16 + a_lrow) * SA +
                                         koff + a_lcol) * 4;
                LDSM_X4(af, addr);
#pragma unroll
                for (int ntp = 0; ntp < 2; ntp++) {
                    MMA_TF32(c[mt][ntp * 2 + 0], af, bf[ntp][0], bf[ntp][1]);
                    MMA_TF32(c[mt][ntp * 2 + 1], af, bf[ntp][2], bf[ntp][3]);
                }
            }
        }

        if (t + 1 < NTILES) {
            store_stage((t + 1) & 1);
            __syncthreads();
        }
    }

    // epilogue: fragment -> gmem (float2 per quad)
#pragma unroll
    for (int mt = 0; mt < MT; mt++) {
#pragma unroll
        for (int nt = 0; nt < 4; nt++) {
            int r0 = block_m + warp_m * WM + mt * 16 + (lane >> 2);
            int col = block_n + warp_n * 32 + nt * 8 + (lane & 3) * 2;
            if (r0 < M)
                *(float2*)&C[(size_t)r0 * NOUT + col] = make_float2(c[mt][nt][0], c[mt][nt][1]);
            int r1 = r0 + 8;
            if (r1 < M)
                *(float2*)&C[(size_t)r1 * NOUT + col] = make_float2(c[mt][nt][2], c[mt][nt][3]);
        }
    }
}

// ---------------------------------------------------------------------------
// CSR gather, fully fused: one warp per node.
// ---------------------------------------------------------------------------
template <int D, bool ACT>
__global__ void gather_csr_kernel(const float* __restrict__ h,
                                  const float* __restrict__ b,
                                  float* __restrict__ out, int N) {
    constexpr int VEC = D / 4;
    constexpr int PER = (VEC + 31) / 32;
    int gw = (blockIdx.x * blockDim.x + threadIdx.x) >> 5;
    int lane = threadIdx.x & 31;
    if (gw >= N) return;

    float dd = g_dinv[gw];
    float w = dd * dd;
    const float4* hd = (const float4*)(h + (size_t)gw * D);

    float4 acc[PER];
#pragma unroll
    for (int j = 0; j < PER; j++) {
        int idx = lane + j * 32;
        if (idx < VEC) {
            float4 v = hd[idx];
            acc[j] = make_float4(v.x * w, v.y * w, v.z * w, v.w * w);
        } else acc[j] = make_float4(0.f, 0.f, 0.f, 0.f);
    }

    int e0 = g_row_off[gw];
    int e1 = g_row_off[gw + 1];
    for (int e = e0; e < e1; e++) {
        int s = __ldg(&g_csr_src[e]);
        float norm = g_dinv[s] * dd;
        const float4* hs = (const float4*)(h + (size_t)s * D);
#pragma unroll
        for (int j = 0; j < PER; j++) {
            int idx = lane + j * 32;
            if (idx < VEC) {
                float4 v = hs[idx];
                acc[j].x = fmaf(norm, v.x, acc[j].x);
                acc[j].y = fmaf(norm, v.y, acc[j].y);
                acc[j].z = fmaf(norm, v.z, acc[j].z);
                acc[j].w = fmaf(norm, v.w, acc[j].w);
            }
        }
    }

    const float4* bb = (const float4*)b;
    float4* op = (float4*)(out + (size_t)gw * D);
#pragma unroll
    for (int j = 0; j < PER; j++) {
        int idx = lane + j * 32;
        if (idx < VEC) {
            float4 v = acc[j];
            float4 B = bb[idx];
            v.x += B.x; v.y += B.y; v.z += B.z; v.w += B.w;
            if (ACT) {
                v.x = v.x > 0.0f ? v.x : SLOPE * v.x;
                v.y = v.y > 0.0f ? v.y : SLOPE * v.y;
                v.z = v.z > 0.0f ? v.z : SLOPE * v.z;
                v.w = v.w > 0.0f ? v.w : SLOPE * v.w;
            }
            op[idx] = v;
        }
    }
}

// ---------------------------------------------------------------------------
// launch
// ---------------------------------------------------------------------------
extern "C" void kernel_launch(void* const* d_in, const int* in_sizes, int n_in,
                              void* d_out, int out_size) {
    const float* x  = (const float*)d_in[0];
    const int*   ei = (const int*)d_in[1];
    const float* W1 = (const float*)d_in[2];
    const float* b1 = (const float*)d_in[3];
    const float* W2 = (const float*)d_in[4];
    const float* b2 = (const float*)d_in[5];
    const float* W3 = (const float*)d_in[6];
    const float* b3 = (const float*)d_in[7];
    float* out = (float*)d_out;

    const int N = in_sizes[0] / DH;
    const int E = in_sizes[1] / 2;
    const int* src = ei;
    const int* dstp = ei + E;

    float* h1 = out;
    float* h2 = out + (size_t)N * DH;
    float* lg = out + 2 * (size_t)N * DH;

    float* hbuf = nullptr;
    cudaGetSymbolAddress((void**)&hbuf, g_h);
    int* degp = nullptr;
    cudaGetSymbolAddress((void**)&degp, g_deg);

    // dynamic smem: 2 stages of (A 128x36 + B BNx36) fp32
    const int SMEM128 = 2 * (128 * 36 * 4 + 128 * 36 * 4);  // 73728
    const int SMEM64  = 2 * (128 * 36 * 4 + 64 * 36 * 4);   // 55296
    cudaFuncSetAttribute(gemm_tf32<128>, cudaFuncAttributeMaxDynamicSharedMemorySize, SMEM128);
    cudaFuncSetAttribute(gemm_tf32<64>,  cudaFuncAttributeMaxDynamicSharedMemorySize, SMEM64);

    // --- degree / dinv / CSR ---
    const int NB = (N + 255) / 256;
    cudaMemsetAsync(degp, 0, N * sizeof(int));
    count_deg_kernel<<<(E + 255) / 256, 256>>>(dstp, E);
    dinv_blocksum_kernel<<<NB, 256>>>(N);
    scan_bsums_kernel<<<1, 256>>>(NB);
    fill_offsets_kernel<<<NB, 256>>>(N, E);
    fill_csr_kernel<<<(E + 255) / 256, 256>>>(src, dstp, E);

    const int gather_blocks = (N + 7) / 8;
    const int tiles_m = (N + 127) / 128;

    // --- layer 1 ---
    gemm_tf32<128><<<dim3(tiles_m, DH / 128), 256, SMEM128>>>(x, W1, hbuf, N, DH);
    gather_csr_kernel<DH, true><<<gather_blocks, 256>>>(hbuf, b1, h1, N);

    // --- layer 2 ---
    gemm_tf32<128><<<dim3(tiles_m, DH / 128), 256, SMEM128>>>(h1, W2, hbuf, N, DH);
    gather_csr_kernel<DH, true><<<gather_blocks, 256>>>(hbuf, b2, h2, N);

    // --- layer 3 ---
    gemm_tf32<64><<<dim3(tiles_m, DOUT / 64), 256, SMEM64>>>(h2, W3, hbuf, N, DOUT);
    gather_csr_kernel<DOUT, false><<<gather_blocks, 256>>>(hbuf, b3, lg, N);
}

// round 12
// speedup vs baseline: 3.6862x; 1.0152x over previous
#include <cuda_runtime.h>
#include <cuda_bf16.h>
#include <cstdint>

#define N_NODES 50000
#define E_MAX   800000
#define DH 256
#define DOUT 64
#define SLOPE 0.01f

// ---------------------------------------------------------------------------
// Scratch (allocation-free rule: __device__ globals)
// ---------------------------------------------------------------------------
__device__ float g_h[(size_t)N_NODES * DH];   // GEMM output per layer
__device__ int   g_deg[N_NODES];
__device__ float g_dinv[N_NODES];
__device__ int   g_row_off[N_NODES + 1];
__device__ int   g_cursor[N_NODES];
__device__ int   g_csr_src[E_MAX];
__device__ int   g_bsum[256];
__device__ int   g_boff[256];

__device__ __forceinline__ uint32_t smem_to_u32(const void* p) {
    uint32_t a;
    asm("{ .reg .u64 t; cvta.to.shared.u64 t, %1; cvt.u32.u64 %0, t; }" : "=r"(a) : "l"(p));
    return a;
}
__device__ __forceinline__ uint32_t f2tf32(float f) {
    uint32_t o;
    asm("cvt.rna.tf32.f32 %0, %1;" : "=r"(o) : "f"(f));
    return o;
}

#define LDSM_X4(R, ADDR) \
    asm volatile("ldmatrix.sync.aligned.m8n8.x4.shared.b16 {%0,%1,%2,%3}, [%4];" \
                 : "=r"((R)[0]), "=r"((R)[1]), "=r"((R)[2]), "=r"((R)[3]) : "r"(ADDR))

#define MMA_TF32(C, A, B0, B1) \
    asm volatile("mma.sync.aligned.m16n8k8.row.col.f32.tf32.tf32.f32 " \
                 "{%0,%1,%2,%3}, {%4,%5,%6,%7}, {%8,%9}, {%0,%1,%2,%3};" \
                 : "+f"((C)[0]), "+f"((C)[1]), "+f"((C)[2]), "+f"((C)[3]) \
                 : "r"((A)[0]), "r"((A)[1]), "r"((A)[2]), "r"((A)[3]), "r"(B0), "r"(B1))

// ---------------------------------------------------------------------------
// degree / CSR build (parallel scan); dinv fused into fill_offsets
// ---------------------------------------------------------------------------
__global__ void count_deg_kernel(const int* __restrict__ dst, int E) {
    int i = blockIdx.x * blockDim.x + threadIdx.x;
    if (i < E) atomicAdd(&g_deg[dst[i]], 1);
}
__global__ void block_sum_kernel(int n) {
    __shared__ int s[256];
    int i = blockIdx.x * 256 + threadIdx.x;
    s[threadIdx.x] = (i < n) ? g_deg[i] : 0;
    __syncthreads();
    for (int o = 128; o > 0; o >>= 1) {
        if (threadIdx.x < o) s[threadIdx.x] += s[threadIdx.x + o];
        __syncthreads();
    }
    if (threadIdx.x == 0) g_bsum[blockIdx.x] = s[0];
}
__global__ void scan_bsums_kernel(int nb) {
    __shared__ int s[256];
    int t = threadIdx.x;
    s[t] = (t < nb) ? g_bsum[t] : 0;
    __syncthreads();
    for (int o = 1; o < 256; o <<= 1) {
        int v = (t >= o) ? s[t - o] : 0;
        __syncthreads();
        s[t] += v;
        __syncthreads();
    }
    if (t < nb) g_boff[t] = (t == 0) ? 0 : s[t - 1];
}
// fused: exclusive offsets + dinv
__global__ void fill_offsets_kernel(int n, int E) {
    __shared__ int s[256];
    int t = threadIdx.x;
    int i = blockIdx.x * 256 + t;
    int d = (i < n) ? g_deg[i] : 0;
    if (i < n) g_dinv[i] = rsqrtf((float)(d + 1));
    s[t] = d;
    __syncthreads();
    for (int o = 1; o < 256; o <<= 1) {
        int v = (t >= o) ? s[t - o] : 0;
        __syncthreads();
        s[t] += v;
        __syncthreads();
    }
    int excl = s[t] - d + g_boff[blockIdx.x];
    if (i < n) { g_row_off[i] = excl; g_cursor[i] = excl; }
    if (i == n - 1) g_row_off[n] = E;
}
__global__ void fill_csr_kernel(const int* __restrict__ src,
                                const int* __restrict__ dst, int E) {
    int i = blockIdx.x * blockDim.x + threadIdx.x;
    if (i < E) {
        int d = dst[i];
        int pos = atomicAdd(&g_cursor[d], 1);
        g_csr_src[pos] = src[i];
    }
}

// ---------------------------------------------------------------------------
// Single-pass TF32 MMA GEMM (unchanged — at HMMA issue ceiling)
// ---------------------------------------------------------------------------
template <int BN>
__global__ void __launch_bounds__(256)
gemm_tf32(const float* __restrict__ A, const float* __restrict__ W,
          float* __restrict__ C, int M, int NOUT) {
    constexpr int BM = 128, KD = 256;
    constexpr int NTILES = KD / 32;
    constexpr int WARPS_N = BN / 32;
    constexpr int WARPS_M = 8 / WARPS_N;
    constexpr int WM = BM / WARPS_M;
    constexpr int MT = WM / 16;
    constexpr int SA = 36;
    constexpr int ABYTES = BM * SA * 4;
    constexpr int BBYTES = BN * SA * 4;
    constexpr int STAGE = ABYTES + BBYTES;
    constexpr int NBL = BN / 32;

    extern __shared__ char smem_raw[];
    const uint32_t sbase = smem_to_u32(smem_raw);

    const int tid = threadIdx.x;
    const int lane = tid & 31;
    const int wid = tid >> 5;
    const int warp_n = wid % WARPS_N;
    const int warp_m = wid / WARPS_N;
    const int block_m = blockIdx.x * BM;
    const int block_n = blockIdx.y * BN;

    float c[MT][4][4];
#pragma unroll
    for (int i = 0; i < MT; i++)
#pragma unroll
        for (int j = 0; j < 4; j++)
#pragma unroll
            for (int q = 0; q < 4; q++) c[i][j][q] = 0.0f;

    const int a_lrow = lane & 15;
    const int a_lcol = (lane >> 4) * 4;
    const int b_lrow = (lane & 7) + ((lane >> 4) * 8);
    const int b_lcol = ((lane >> 3) & 1) * 4;

    float4 areg[4];
    float4 breg[NBL];
    const int a_r0 = tid >> 3;
    const int a_c4 = tid & 7;

    auto load_global = [&](int t) {
        int k8 = t * 8;
#pragma unroll
        for (int i = 0; i < 4; i++) {
            int gm = block_m + a_r0 + 32 * i;
            int rowc = gm < M ? gm : M - 1;
            areg[i] = __ldg((const float4*)A + (size_t)rowc * 64 + k8 + a_c4);
        }
#pragma unroll
        for (int j = 0; j < NBL; j++) {
            int flat = tid + 256 * j;
            int row = flat >> 3, c4 = flat & 7;
            breg[j] = __ldg((const float4*)W + (size_t)(block_n + row) * 64 + k8 + c4);
        }
    };

    auto store_stage = [&](int st) {
        uint32_t* ab = (uint32_t*)(smem_raw + st * STAGE);
        uint32_t* bb = (uint32_t*)(smem_raw + st * STAGE + ABYTES);
#pragma unroll
        for (int i = 0; i < 4; i++) {
            uint32_t off = (uint32_t)(a_r0 + 32 * i) * SA + a_c4 * 4;
            float4 f = areg[i];
            *(uint4*)(ab + off) = make_uint4(f2tf32(f.x), f2tf32(f.y), f2tf32(f.z), f2tf32(f.w));
        }
#pragma unroll
        for (int j = 0; j < NBL; j++) {
            int flat = tid + 256 * j;
            uint32_t off = (uint32_t)(flat >> 3) * SA + (flat & 7) * 4;
            float4 f = breg[j];
            *(uint4*)(bb + off) = make_uint4(f2tf32(f.x), f2tf32(f.y), f2tf32(f.z), f2tf32(f.w));
        }
    };

    load_global(0);
    store_stage(0);
    __syncthreads();

    for (int t = 0; t < NTILES; t++) {
        int cur = t & 1;
        if (t + 1 < NTILES) load_global(t + 1);

        uint32_t abase = sbase + cur * STAGE;
        uint32_t bbase = abase + ABYTES;

#pragma unroll
        for (int kb = 0; kb < 4; kb++) {
            int koff = kb * 8;
            uint32_t bf[2][4];
#pragma unroll
            for (int ntp = 0; ntp < 2; ntp++) {
                uint32_t addr = bbase + ((uint32_t)(warp_n * 32 + ntp * 16 + b_lrow) * SA +
                                         koff + b_lcol) * 4;
                LDSM_X4(bf[ntp], addr);
            }
#pragma unroll
            for (int mt = 0; mt < MT; mt++) {
                uint32_t af[4];
                uint32_t addr = abase + ((uint32_t)(warp_m * WM + mt * 16 + a_lrow) * SA +
                                         koff + a_lcol) * 4;
                LDSM_X4(af, addr);
#pragma unroll
                for (int ntp = 0; ntp < 2; ntp++) {
                    MMA_TF32(c[mt][ntp * 2 + 0], af, bf[ntp][0], bf[ntp][1]);
                    MMA_TF32(c[mt][ntp * 2 + 1], af, bf[ntp][2], bf[ntp][3]);
                }
            }
        }

        if (t + 1 < NTILES) {
            store_stage((t + 1) & 1);
            __syncthreads();
        }
    }

#pragma unroll
    for (int mt = 0; mt < MT; mt++) {
#pragma unroll
        for (int nt = 0; nt < 4; nt++) {
            int r0 = block_m + warp_m * WM + mt * 16 + (lane >> 2);
            int col = block_n + warp_n * 32 + nt * 8 + (lane & 3) * 2;
            if (r0 < M)
                *(float2*)&C[(size_t)r0 * NOUT + col] = make_float2(c[mt][nt][0], c[mt][nt][1]);
            int r1 = r0 + 8;
            if (r1 < M)
                *(float2*)&C[(size_t)r1 * NOUT + col] = make_float2(c[mt][nt][2], c[mt][nt][3]);
        }
    }
}

// ---------------------------------------------------------------------------
// CSR gather D=256: one warp per node, 2-edge unroll for LDG MLP.
// ---------------------------------------------------------------------------
template <bool ACT>
__global__ void gather_csr_d256(const float* __restrict__ h,
                                const float* __restrict__ b,
                                float* __restrict__ out, int N) {
    int gw = (blockIdx.x * blockDim.x + threadIdx.x) >> 5;
    int lane = threadIdx.x & 31;
    if (gw >= N) return;

    float dd = g_dinv[gw];
    float w = dd * dd;
    const float4* hd = (const float4*)(h + (size_t)gw * DH);

    float4 a0, a1;
    {
        float4 v0 = hd[lane];
        float4 v1 = hd[lane + 32];
        a0 = make_float4(v0.x * w, v0.y * w, v0.z * w, v0.w * w);
        a1 = make_float4(v1.x * w, v1.y * w, v1.z * w, v1.w * w);
    }

    int e0 = g_row_off[gw];
    int e1 = g_row_off[gw + 1];
    int e = e0;
    for (; e + 1 < e1; e += 2) {
        int s0 = __ldg(&g_csr_src[e]);
        int s1 = __ldg(&g_csr_src[e + 1]);
        float n0 = g_dinv[s0] * dd;
        float n1 = g_dinv[s1] * dd;
        const float4* h0 = (const float4*)(h + (size_t)s0 * DH);
        const float4* h1 = (const float4*)(h + (size_t)s1 * DH);
        float4 u0 = h0[lane];
        float4 u1 = h0[lane + 32];
        float4 v0 = h1[lane];
        float4 v1 = h1[lane + 32];
        a0.x = fmaf(n0, u0.x, a0.x); a0.y = fmaf(n0, u0.y, a0.y);
        a0.z = fmaf(n0, u0.z, a0.z); a0.w = fmaf(n0, u0.w, a0.w);
        a1.x = fmaf(n0, u1.x, a1.x); a1.y = fmaf(n0, u1.y, a1.y);
        a1.z = fmaf(n0, u1.z, a1.z); a1.w = fmaf(n0, u1.w, a1.w);
        a0.x = fmaf(n1, v0.x, a0.x); a0.y = fmaf(n1, v0.y, a0.y);
        a0.z = fmaf(n1, v0.z, a0.z); a0.w = fmaf(n1, v0.w, a0.w);
        a1.x = fmaf(n1, v1.x, a1.x); a1.y = fmaf(n1, v1.y, a1.y);
        a1.z = fmaf(n1, v1.z, a1.z); a1.w = fmaf(n1, v1.w, a1.w);
    }
    if (e < e1) {
        int s0 = __ldg(&g_csr_src[e]);
        float n0 = g_dinv[s0] * dd;
        const float4* h0 = (const float4*)(h + (size_t)s0 * DH);
        float4 u0 = h0[lane];
        float4 u1 = h0[lane + 32];
        a0.x = fmaf(n0, u0.x, a0.x); a0.y = fmaf(n0, u0.y, a0.y);
        a0.z = fmaf(n0, u0.z, a0.z); a0.w = fmaf(n0, u0.w, a0.w);
        a1.x = fmaf(n0, u1.x, a1.x); a1.y = fmaf(n0, u1.y, a1.y);
        a1.z = fmaf(n0, u1.z, a1.z); a1.w = fmaf(n0, u1.w, a1.w);
    }

    const float4* bb = (const float4*)b;
    float4* op = (float4*)(out + (size_t)gw * DH);
    float4 B0 = bb[lane], B1 = bb[lane + 32];
    a0.x += B0.x; a0.y += B0.y; a0.z += B0.z; a0.w += B0.w;
    a1.x += B1.x; a1.y += B1.y; a1.z += B1.z; a1.w += B1.w;
    if (ACT) {
        a0.x = a0.x > 0.f ? a0.x : SLOPE * a0.x;
        a0.y = a0.y > 0.f ? a0.y : SLOPE * a0.y;
        a0.z = a0.z > 0.f ? a0.z : SLOPE * a0.z;
        a0.w = a0.w > 0.f ? a0.w : SLOPE * a0.w;
        a1.x = a1.x > 0.f ? a1.x : SLOPE * a1.x;
        a1.y = a1.y > 0.f ? a1.y : SLOPE * a1.y;
        a1.z = a1.z > 0.f ? a1.z : SLOPE * a1.z;
        a1.w = a1.w > 0.f ? a1.w : SLOPE * a1.w;
    }
    op[lane] = a0;
    op[lane + 32] = a1;
}

// ---------------------------------------------------------------------------
// CSR gather D=64: one warp per node, both half-warps active —
// lanes 0-15 even edges, lanes 16-31 odd edges, shfl-combine at the end.
// ---------------------------------------------------------------------------
template <bool ACT>
__global__ void gather_csr_d64(const float* __restrict__ h,
                               const float* __restrict__ b,
                               float* __restrict__ out, int N) {
    int gw = (blockIdx.x * blockDim.x + threadIdx.x) >> 5;
    int lane = threadIdx.x & 31;
    int l16 = lane & 15;
    int half = lane >> 4;
    if (gw >= N) return;

    float dd = g_dinv[gw];
    int e0 = g_row_off[gw];
    int e1 = g_row_off[gw + 1];

    float4 acc = make_float4(0.f, 0.f, 0.f, 0.f);
    for (int e = e0 + half; e < e1; e += 2) {
        int s = __ldg(&g_csr_src[e]);
        float norm = g_dinv[s] * dd;
        float4 v = ((const float4*)(h + (size_t)s * DOUT))[l16];
        acc.x = fmaf(norm, v.x, acc.x);
        acc.y = fmaf(norm, v.y, acc.y);
        acc.z = fmaf(norm, v.z, acc.z);
        acc.w = fmaf(norm, v.w, acc.w);
    }
    // combine halves
    acc.x += __shfl_xor_sync(0xffffffffu, acc.x, 16);
    acc.y += __shfl_xor_sync(0xffffffffu, acc.y, 16);
    acc.z += __shfl_xor_sync(0xffffffffu, acc.z, 16);
    acc.w += __shfl_xor_sync(0xffffffffu, acc.w, 16);

    if (half == 0) {
        float w = dd * dd;
        float4 sv = ((const float4*)(h + (size_t)gw * DOUT))[l16];
        float4 B = ((const float4*)b)[l16];
        acc.x = fmaf(w, sv.x, acc.x) + B.x;
        acc.y = fmaf(w, sv.y, acc.y) + B.y;
        acc.z = fmaf(w, sv.z, acc.z) + B.z;
        acc.w = fmaf(w, sv.w, acc.w) + B.w;
        if (ACT) {
            acc.x = acc.x > 0.f ? acc.x : SLOPE * acc.x;
            acc.y = acc.y > 0.f ? acc.y : SLOPE * acc.y;
            acc.z = acc.z > 0.f ? acc.z : SLOPE * acc.z;
            acc.w = acc.w > 0.f ? acc.w : SLOPE * acc.w;
        }
        ((float4*)(out + (size_t)gw * DOUT))[l16] = acc;
    }
}

// ---------------------------------------------------------------------------
// launch
// ---------------------------------------------------------------------------
extern "C" void kernel_launch(void* const* d_in, const int* in_sizes, int n_in,
                              void* d_out, int out_size) {
    const float* x  = (const float*)d_in[0];
    const int*   ei = (const int*)d_in[1];
    const float* W1 = (const float*)d_in[2];
    const float* b1 = (const float*)d_in[3];
    const float* W2 = (const float*)d_in[4];
    const float* b2 = (const float*)d_in[5];
    const float* W3 = (const float*)d_in[6];
    const float* b3 = (const float*)d_in[7];
    float* out = (float*)d_out;

    const int N = in_sizes[0] / DH;
    const int E = in_sizes[1] / 2;
    const int* src = ei;
    const int* dstp = ei + E;

    float* h1 = out;
    float* h2 = out + (size_t)N * DH;
    float* lg = out + 2 * (size_t)N * DH;

    float* hbuf = nullptr;
    cudaGetSymbolAddress((void**)&hbuf, g_h);
    int* degp = nullptr;
    cudaGetSymbolAddress((void**)&degp, g_deg);

    const int SMEM128 = 2 * (128 * 36 * 4 + 128 * 36 * 4);  // 73728
    const int SMEM64  = 2 * (128 * 36 * 4 + 64 * 36 * 4);   // 55296
    cudaFuncSetAttribute(gemm_tf32<128>, cudaFuncAttributeMaxDynamicSharedMemorySize, SMEM128);
    cudaFuncSetAttribute(gemm_tf32<64>,  cudaFuncAttributeMaxDynamicSharedMemorySize, SMEM64);

    // --- degree / dinv / CSR ---
    const int NB = (N + 255) / 256;
    cudaMemsetAsync(degp, 0, N * sizeof(int));
    count_deg_kernel<<<(E + 255) / 256, 256>>>(dstp, E);
    block_sum_kernel<<<NB, 256>>>(N);
    scan_bsums_kernel<<<1, 256>>>(NB);
    fill_offsets_kernel<<<NB, 256>>>(N, E);
    fill_csr_kernel<<<(E + 255) / 256, 256>>>(src, dstp, E);

    const int gather_blocks = (N + 7) / 8;
    const int tiles_m = (N + 127) / 128;

    // --- layer 1 ---
    gemm_tf32<128><<<dim3(tiles_m, DH / 128), 256, SMEM128>>>(x, W1, hbuf, N, DH);
    gather_csr_d256<true><<<gather_blocks, 256>>>(hbuf, b1, h1, N);

    // --- layer 2 ---
    gemm_tf32<128><<<dim3(tiles_m, DH / 128), 256, SMEM128>>>(h1, W2, hbuf, N, DH);
    gather_csr_d256<true><<<gather_blocks, 256>>>(hbuf, b2, h2, N);

    // --- layer 3 ---
    gemm_tf32<64><<<dim3(tiles_m, DOUT / 64), 256, SMEM64>>>(h2, W3, hbuf, N, DOUT);
    gather_csr_d64<false><<<gather_blocks, 256>>>(hbuf, b3, lg, N);
}

// round 13
// speedup vs baseline: 3.9980x; 1.0846x over previous
#include <cuda_runtime.h>
#include <cuda_fp16.h>
#include <cstdint>

#define N_NODES 50000
#define E_MAX   800000
#define DH 256
#define DOUT 64
#define SLOPE 0.01f

// ---------------------------------------------------------------------------
// Scratch (allocation-free rule: __device__ globals)
// ---------------------------------------------------------------------------
__device__ __half g_h[(size_t)N_NODES * DH];  // GEMM output per layer (fp16)
__device__ int    g_deg[N_NODES];
__device__ float  g_dinv[N_NODES];
__device__ int    g_row_off[N_NODES + 1];
__device__ int    g_cursor[N_NODES];
__device__ int    g_csr_src[E_MAX];
__device__ int    g_bsum[256];
__device__ int    g_boff[256];

__device__ __forceinline__ uint32_t smem_to_u32(const void* p) {
    uint32_t a;
    asm("{ .reg .u64 t; cvta.to.shared.u64 t, %1; cvt.u32.u64 %0, t; }" : "=r"(a) : "l"(p));
    return a;
}
__device__ __forceinline__ uint32_t f2tf32(float f) {
    uint32_t o;
    asm("cvt.rna.tf32.f32 %0, %1;" : "=r"(o) : "f"(f));
    return o;
}

#define LDSM_X4(R, ADDR) \
    asm volatile("ldmatrix.sync.aligned.m8n8.x4.shared.b16 {%0,%1,%2,%3}, [%4];" \
                 : "=r"((R)[0]), "=r"((R)[1]), "=r"((R)[2]), "=r"((R)[3]) : "r"(ADDR))

#define MMA_TF32(C, A, B0, B1) \
    asm volatile("mma.sync.aligned.m16n8k8.row.col.f32.tf32.tf32.f32 " \
                 "{%0,%1,%2,%3}, {%4,%5,%6,%7}, {%8,%9}, {%0,%1,%2,%3};" \
                 : "+f"((C)[0]), "+f"((C)[1]), "+f"((C)[2]), "+f"((C)[3]) \
                 : "r"((A)[0]), "r"((A)[1]), "r"((A)[2]), "r"((A)[3]), "r"(B0), "r"(B1))

// ---------------------------------------------------------------------------
// degree / CSR build (parallel scan); dinv fused into fill_offsets
// ---------------------------------------------------------------------------
__global__ void count_deg_kernel(const int* __restrict__ dst, int E) {
    int i = blockIdx.x * blockDim.x + threadIdx.x;
    if (i < E) atomicAdd(&g_deg[dst[i]], 1);
}
__global__ void block_sum_kernel(int n) {
    __shared__ int s[256];
    int i = blockIdx.x * 256 + threadIdx.x;
    s[threadIdx.x] = (i < n) ? g_deg[i] : 0;
    __syncthreads();
    for (int o = 128; o > 0; o >>= 1) {
        if (threadIdx.x < o) s[threadIdx.x] += s[threadIdx.x + o];
        __syncthreads();
    }
    if (threadIdx.x == 0) g_bsum[blockIdx.x] = s[0];
}
__global__ void scan_bsums_kernel(int nb) {
    __shared__ int s[256];
    int t = threadIdx.x;
    s[t] = (t < nb) ? g_bsum[t] : 0;
    __syncthreads();
    for (int o = 1; o < 256; o <<= 1) {
        int v = (t >= o) ? s[t - o] : 0;
        __syncthreads();
        s[t] += v;
        __syncthreads();
    }
    if (t < nb) g_boff[t] = (t == 0) ? 0 : s[t - 1];
}
__global__ void fill_offsets_kernel(int n, int E) {
    __shared__ int s[256];
    int t = threadIdx.x;
    int i = blockIdx.x * 256 + t;
    int d = (i < n) ? g_deg[i] : 0;
    if (i < n) g_dinv[i] = rsqrtf((float)(d + 1));
    s[t] = d;
    __syncthreads();
    for (int o = 1; o < 256; o <<= 1) {
        int v = (t >= o) ? s[t - o] : 0;
        __syncthreads();
        s[t] += v;
        __syncthreads();
    }
    int excl = s[t] - d + g_boff[blockIdx.x];
    if (i < n) { g_row_off[i] = excl; g_cursor[i] = excl; }
    if (i == n - 1) g_row_off[n] = E;
}
__global__ void fill_csr_kernel(const int* __restrict__ src,
                                const int* __restrict__ dst, int E) {
    int i = blockIdx.x * blockDim.x + threadIdx.x;
    if (i < E) {
        int d = dst[i];
        int pos = atomicAdd(&g_cursor[d], 1);
        g_csr_src[pos] = src[i];
    }
}

// ---------------------------------------------------------------------------
// Single-pass TF32 MMA GEMM; epilogue stores C in fp16 (half2).
// ---------------------------------------------------------------------------
template <int BN>
__global__ void __launch_bounds__(256)
gemm_tf32(const float* __restrict__ A, const float* __restrict__ W,
          __half* __restrict__ C, int M, int NOUT) {
    constexpr int BM = 128, KD = 256;
    constexpr int NTILES = KD / 32;
    constexpr int WARPS_N = BN / 32;
    constexpr int WARPS_M = 8 / WARPS_N;
    constexpr int WM = BM / WARPS_M;
    constexpr int MT = WM / 16;
    constexpr int SA = 36;
    constexpr int ABYTES = BM * SA * 4;
    constexpr int BBYTES = BN * SA * 4;
    constexpr int STAGE = ABYTES + BBYTES;
    constexpr int NBL = BN / 32;

    extern __shared__ char smem_raw[];
    const uint32_t sbase = smem_to_u32(smem_raw);

    const int tid = threadIdx.x;
    const int lane = tid & 31;
    const int wid = tid >> 5;
    const int warp_n = wid % WARPS_N;
    const int warp_m = wid / WARPS_N;
    const int block_m = blockIdx.x * BM;
    const int block_n = blockIdx.y * BN;

    float c[MT][4][4];
#pragma unroll
    for (int i = 0; i < MT; i++)
#pragma unroll
        for (int j = 0; j < 4; j++)
#pragma unroll
            for (int q = 0; q < 4; q++) c[i][j][q] = 0.0f;

    const int a_lrow = lane & 15;
    const int a_lcol = (lane >> 4) * 4;
    const int b_lrow = (lane & 7) + ((lane >> 4) * 8);
    const int b_lcol = ((lane >> 3) & 1) * 4;

    float4 areg[4];
    float4 breg[NBL];
    const int a_r0 = tid >> 3;
    const int a_c4 = tid & 7;

    auto load_global = [&](int t) {
        int k8 = t * 8;
#pragma unroll
        for (int i = 0; i < 4; i++) {
            int gm = block_m + a_r0 + 32 * i;
            int rowc = gm < M ? gm : M - 1;
            areg[i] = __ldg((const float4*)A + (size_t)rowc * 64 + k8 + a_c4);
        }
#pragma unroll
        for (int j = 0; j < NBL; j++) {
            int flat = tid + 256 * j;
            int row = flat >> 3, c4 = flat & 7;
            breg[j] = __ldg((const float4*)W + (size_t)(block_n + row) * 64 + k8 + c4);
        }
    };

    auto store_stage = [&](int st) {
        uint32_t* ab = (uint32_t*)(smem_raw + st * STAGE);
        uint32_t* bb = (uint32_t*)(smem_raw + st * STAGE + ABYTES);
#pragma unroll
        for (int i = 0; i < 4; i++) {
            uint32_t off = (uint32_t)(a_r0 + 32 * i) * SA + a_c4 * 4;
            float4 f = areg[i];
            *(uint4*)(ab + off) = make_uint4(f2tf32(f.x), f2tf32(f.y), f2tf32(f.z), f2tf32(f.w));
        }
#pragma unroll
        for (int j = 0; j < NBL; j++) {
            int flat = tid + 256 * j;
            uint32_t off = (uint32_t)(flat >> 3) * SA + (flat & 7) * 4;
            float4 f = breg[j];
            *(uint4*)(bb + off) = make_uint4(f2tf32(f.x), f2tf32(f.y), f2tf32(f.z), f2tf32(f.w));
        }
    };

    load_global(0);
    store_stage(0);
    __syncthreads();

    for (int t = 0; t < NTILES; t++) {
        int cur = t & 1;
        if (t + 1 < NTILES) load_global(t + 1);

        uint32_t abase = sbase + cur * STAGE;
        uint32_t bbase = abase + ABYTES;

#pragma unroll
        for (int kb = 0; kb < 4; kb++) {
            int koff = kb * 8;
            uint32_t bf[2][4];
#pragma unroll
            for (int ntp = 0; ntp < 2; ntp++) {
                uint32_t addr = bbase + ((uint32_t)(warp_n * 32 + ntp * 16 + b_lrow) * SA +
                                         koff + b_lcol) * 4;
                LDSM_X4(bf[ntp], addr);
            }
#pragma unroll
            for (int mt = 0; mt < MT; mt++) {
                uint32_t af[4];
                uint32_t addr = abase + ((uint32_t)(warp_m * WM + mt * 16 + a_lrow) * SA +
                                         koff + a_lcol) * 4;
                LDSM_X4(af, addr);
#pragma unroll
                for (int ntp = 0; ntp < 2; ntp++) {
                    MMA_TF32(c[mt][ntp * 2 + 0], af, bf[ntp][0], bf[ntp][1]);
                    MMA_TF32(c[mt][ntp * 2 + 1], af, bf[ntp][2], bf[ntp][3]);
                }
            }
        }

        if (t + 1 < NTILES) {
            store_stage((t + 1) & 1);
            __syncthreads();
        }
    }

    // epilogue: half2 per quad
#pragma unroll
    for (int mt = 0; mt < MT; mt++) {
#pragma unroll
        for (int nt = 0; nt < 4; nt++) {
            int r0 = block_m + warp_m * WM + mt * 16 + (lane >> 2);
            int col = block_n + warp_n * 32 + nt * 8 + (lane & 3) * 2;
            if (r0 < M)
                *(__half2*)&C[(size_t)r0 * NOUT + col] = __floats2half2_rn(c[mt][nt][0], c[mt][nt][1]);
            int r1 = r0 + 8;
            if (r1 < M)
                *(__half2*)&C[(size_t)r1 * NOUT + col] = __floats2half2_rn(c[mt][nt][2], c[mt][nt][3]);
        }
    }
}

// ---------------------------------------------------------------------------
// helpers: unpack uint4 of 8 halves -> 8 floats; fma into acc
// ---------------------------------------------------------------------------
__device__ __forceinline__ void h8_unpack(const uint4& u, float* f) {
    float2 p0 = __half22float2(*(const __half2*)&u.x);
    float2 p1 = __half22float2(*(const __half2*)&u.y);
    float2 p2 = __half22float2(*(const __half2*)&u.z);
    float2 p3 = __half22float2(*(const __half2*)&u.w);
    f[0] = p0.x; f[1] = p0.y; f[2] = p1.x; f[3] = p1.y;
    f[4] = p2.x; f[5] = p2.y; f[6] = p3.x; f[7] = p3.y;
}

// ---------------------------------------------------------------------------
// CSR gather D=256 (fp16 h): one warp per node, 8 halves (1 uint4) per lane.
// ---------------------------------------------------------------------------
template <bool ACT>
__global__ void gather_csr_d256(const __half* __restrict__ h,
                                const float* __restrict__ b,
                                float* __restrict__ out, int N) {
    int gw = (blockIdx.x * blockDim.x + threadIdx.x) >> 5;
    int lane = threadIdx.x & 31;
    if (gw >= N) return;

    float dd = g_dinv[gw];
    float w = dd * dd;

    float acc[8], f[8];
    {
        uint4 sv = ((const uint4*)(h + (size_t)gw * DH))[lane];
        h8_unpack(sv, f);
#pragma unroll
        for (int i = 0; i < 8; i++) acc[i] = w * f[i];
    }

    int e0 = g_row_off[gw];
    int e1 = g_row_off[gw + 1];
    int e = e0;
    for (; e + 1 < e1; e += 2) {
        int s0 = __ldg(&g_csr_src[e]);
        int s1 = __ldg(&g_csr_src[e + 1]);
        float n0 = g_dinv[s0] * dd;
        float n1 = g_dinv[s1] * dd;
        uint4 u0 = ((const uint4*)(h + (size_t)s0 * DH))[lane];
        uint4 u1 = ((const uint4*)(h + (size_t)s1 * DH))[lane];
        h8_unpack(u0, f);
#pragma unroll
        for (int i = 0; i < 8; i++) acc[i] = fmaf(n0, f[i], acc[i]);
        h8_unpack(u1, f);
#pragma unroll
        for (int i = 0; i < 8; i++) acc[i] = fmaf(n1, f[i], acc[i]);
    }
    if (e < e1) {
        int s0 = __ldg(&g_csr_src[e]);
        float n0 = g_dinv[s0] * dd;
        uint4 u0 = ((const uint4*)(h + (size_t)s0 * DH))[lane];
        h8_unpack(u0, f);
#pragma unroll
        for (int i = 0; i < 8; i++) acc[i] = fmaf(n0, f[i], acc[i]);
    }

    const float4* bb = (const float4*)b;
    float4* op = (float4*)(out + (size_t)gw * DH);
    float4 B0 = bb[lane * 2], B1 = bb[lane * 2 + 1];
    float4 o0 = make_float4(acc[0] + B0.x, acc[1] + B0.y, acc[2] + B0.z, acc[3] + B0.w);
    float4 o1 = make_float4(acc[4] + B1.x, acc[5] + B1.y, acc[6] + B1.z, acc[7] + B1.w);
    if (ACT) {
        o0.x = o0.x > 0.f ? o0.x : SLOPE * o0.x;
        o0.y = o0.y > 0.f ? o0.y : SLOPE * o0.y;
        o0.z = o0.z > 0.f ? o0.z : SLOPE * o0.z;
        o0.w = o0.w > 0.f ? o0.w : SLOPE * o0.w;
        o1.x = o1.x > 0.f ? o1.x : SLOPE * o1.x;
        o1.y = o1.y > 0.f ? o1.y : SLOPE * o1.y;
        o1.z = o1.z > 0.f ? o1.z : SLOPE * o1.z;
        o1.w = o1.w > 0.f ? o1.w : SLOPE * o1.w;
    }
    op[lane * 2] = o0;
    op[lane * 2 + 1] = o1;
}

// ---------------------------------------------------------------------------
// CSR gather D=64 (fp16 h): one warp per node, half-warps split even/odd edges.
// Each active lane handles 4 halves (1 uint2).
// ---------------------------------------------------------------------------
template <bool ACT>
__global__ void gather_csr_d64(const __half* __restrict__ h,
                               const float* __restrict__ b,
                               float* __restrict__ out, int N) {
    int gw = (blockIdx.x * blockDim.x + threadIdx.x) >> 5;
    int lane = threadIdx.x & 31;
    int l16 = lane & 15;
    int half = lane >> 4;
    if (gw >= N) return;

    float dd = g_dinv[gw];
    int e0 = g_row_off[gw];
    int e1 = g_row_off[gw + 1];

    float acc[4] = {0.f, 0.f, 0.f, 0.f};
    for (int e = e0 + half; e < e1; e += 2) {
        int s = __ldg(&g_csr_src[e]);
        float norm = g_dinv[s] * dd;
        uint2 u = ((const uint2*)(h + (size_t)s * DOUT))[l16];
        float2 p0 = __half22float2(*(const __half2*)&u.x);
        float2 p1 = __half22float2(*(const __half2*)&u.y);
        acc[0] = fmaf(norm, p0.x, acc[0]);
        acc[1] = fmaf(norm, p0.y, acc[1]);
        acc[2] = fmaf(norm, p1.x, acc[2]);
        acc[3] = fmaf(norm, p1.y, acc[3]);
    }
#pragma unroll
    for (int i = 0; i < 4; i++)
        acc[i] += __shfl_xor_sync(0xffffffffu, acc[i], 16);

    if (half == 0) {
        float w = dd * dd;
        uint2 u = ((const uint2*)(h + (size_t)gw * DOUT))[l16];
        float2 p0 = __half22float2(*(const __half2*)&u.x);
        float2 p1 = __half22float2(*(const __half2*)&u.y);
        float4 B = ((const float4*)b)[l16];
        float4 o;
        o.x = fmaf(w, p0.x, acc[0]) + B.x;
        o.y = fmaf(w, p0.y, acc[1]) + B.y;
        o.z = fmaf(w, p1.x, acc[2]) + B.z;
        o.w = fmaf(w, p1.y, acc[3]) + B.w;
        if (ACT) {
            o.x = o.x > 0.f ? o.x : SLOPE * o.x;
            o.y = o.y > 0.f ? o.y : SLOPE * o.y;
            o.z = o.z > 0.f ? o.z : SLOPE * o.z;
            o.w = o.w > 0.f ? o.w : SLOPE * o.w;
        }
        ((float4*)(out + (size_t)gw * DOUT))[l16] = o;
    }
}

// ---------------------------------------------------------------------------
// launch
// ---------------------------------------------------------------------------
extern "C" void kernel_launch(void* const* d_in, const int* in_sizes, int n_in,
                              void* d_out, int out_size) {
    const float* x  = (const float*)d_in[0];
    const int*   ei = (const int*)d_in[1];
    const float* W1 = (const float*)d_in[2];
    const float* b1 = (const float*)d_in[3];
    const float* W2 = (const float*)d_in[4];
    const float* b2 = (const float*)d_in[5];
    const float* W3 = (const float*)d_in[6];
    const float* b3 = (const float*)d_in[7];
    float* out = (float*)d_out;

    const int N = in_sizes[0] / DH;
    const int E = in_sizes[1] / 2;
    const int* src = ei;
    const int* dstp = ei + E;

    float* h1 = out;
    float* h2 = out + (size_t)N * DH;
    float* lg = out + 2 * (size_t)N * DH;

    __half* hbuf = nullptr;
    cudaGetSymbolAddress((void**)&hbuf, g_h);
    int* degp = nullptr;
    cudaGetSymbolAddress((void**)&degp, g_deg);

    const int SMEM128 = 2 * (128 * 36 * 4 + 128 * 36 * 4);  // 73728
    const int SMEM64  = 2 * (128 * 36 * 4 + 64 * 36 * 4);   // 55296
    cudaFuncSetAttribute(gemm_tf32<128>, cudaFuncAttributeMaxDynamicSharedMemorySize, SMEM128);
    cudaFuncSetAttribute(gemm_tf32<64>,  cudaFuncAttributeMaxDynamicSharedMemorySize, SMEM64);

    // --- degree / dinv / CSR ---
    const int NB = (N + 255) / 256;
    cudaMemsetAsync(degp, 0, N * sizeof(int));
    count_deg_kernel<<<(E + 255) / 256, 256>>>(dstp, E);
    block_sum_kernel<<<NB, 256>>>(N);
    scan_bsums_kernel<<<1, 256>>>(NB);
    fill_offsets_kernel<<<NB, 256>>>(N, E);
    fill_csr_kernel<<<(E + 255) / 256, 256>>>(src, dstp, E);

    const int gather_blocks = (N + 7) / 8;
    const int tiles_m = (N + 127) / 128;

    // --- layer 1 ---
    gemm_tf32<128><<<dim3(tiles_m, DH / 128), 256, SMEM128>>>(x, W1, hbuf, N, DH);
    gather_csr_d256<true><<<gather_blocks, 256>>>(hbuf, b1, h1, N);

    // --- layer 2 ---
    gemm_tf32<128><<<dim3(tiles_m, DH / 128), 256, SMEM128>>>(h1, W2, hbuf, N, DH);
    gather_csr_d256<true><<<gather_blocks, 256>>>(hbuf, b2, h2, N);

    // --- layer 3 ---
    gemm_tf32<64><<<dim3(tiles_m, DOUT / 64), 256, SMEM64>>>(h2, W3, hbuf, N, DOUT);
    gather_csr_d64<false><<<gather_blocks, 256>>>(hbuf, b3, lg, N);
}